// round 14
// baseline (speedup 1.0000x reference)
#include <cuda_runtime.h>
#include <math.h>
#include <stdint.h>

// ---------------------------------------------------------------------------
// Problem constants
// ---------------------------------------------------------------------------
constexpr int B_  = 64;
constexpr int H_  = 1024;
constexpr int E_  = 512;
constexpr int V_  = 50257;
constexpr int KV_ = 1000;
constexpr int L_  = 512;
constexpr int G4H = 4 * H_;   // 4096

// ---------------------------------------------------------------------------
// Scratch arena
// ---------------------------------------------------------------------------
constexpr long OFF_GATES = 0;
constexpr long OFF_HB    = OFF_GATES + (long)B_ * G4H;
constexpr long OFF_U1    = OFF_HB    + (long)B_ * E_;
constexpr long OFF_U2    = OFF_U1    + (long)B_ * L_ * E_;   // attn dot partials
constexpr long OFF_SC    = OFF_U2    + (long)B_ * L_ * E_;
constexpr long OFF_HCTX  = OFF_SC    + (long)B_ * L_;
constexpr long OFF_KPART = OFF_HCTX  + (long)B_ * H_;
constexpr long OFF_BPART = OFF_KPART + (long)KV_ * E_;
constexpr long OFF_UK1   = OFF_BPART + (long)B_ * E_;
constexpr long OFF_UK2   = OFF_UK1   + (long)B_ * KV_ * E_;  // key dot partials
constexpr long OFF_VK    = OFF_UK2   + (long)B_ * KV_ * E_;
constexpr long OFF_LSM   = OFF_VK    + (long)B_ * KV_;
constexpr long SCRATCH_TOTAL = OFF_LSM + 2048;

__device__ __align__(16) float g_scratch[SCRATCH_TOTAL];

// ---------------------------------------------------------------------------
// Helpers
// ---------------------------------------------------------------------------
static __device__ __forceinline__ float sigmoidf_(float x) {
    return 1.0f / (1.0f + expf(-x));
}

static __device__ __forceinline__ uint32_t smem_u32(const void* p) {
    return (uint32_t)__cvta_generic_to_shared(p);
}

static __device__ __forceinline__ void cp_async16(uint32_t dst, const void* src, int szBytes) {
    asm volatile("cp.async.cg.shared.global [%0], [%1], 16, %2;\n"
                 :: "r"(dst), "l"(src), "r"(szBytes) : "memory");
}

static __device__ __forceinline__ void cp_async4(uint32_t dst, const void* src, int szBytes) {
    asm volatile("cp.async.ca.shared.global [%0], [%1], 4, %2;\n"
                 :: "r"(dst), "l"(src), "r"(szBytes) : "memory");
}

static __device__ __forceinline__ float blockReduceMax(float v, float* red, int tid) {
    #pragma unroll
    for (int o = 16; o; o >>= 1) v = fmaxf(v, __shfl_xor_sync(0xffffffffu, v, o));
    if ((tid & 31) == 0) red[tid >> 5] = v;
    __syncthreads();
    int nw = blockDim.x >> 5;
    float r = red[0];
    for (int i = 1; i < nw; i++) r = fmaxf(r, red[i]);
    __syncthreads();
    return r;
}

static __device__ __forceinline__ float blockReduceSum(float v, float* red, int tid) {
    #pragma unroll
    for (int o = 16; o; o >>= 1) v += __shfl_xor_sync(0xffffffffu, v, o);
    if ((tid & 31) == 0) red[tid >> 5] = v;
    __syncthreads();
    int nw = blockDim.x >> 5;
    float r = red[0];
    for (int i = 1; i < nw; i++) r += red[i];
    __syncthreads();
    return r;
}

// ---------------------------------------------------------------------------
// LSTM gates
// ---------------------------------------------------------------------------
__global__ void gates_k(const int* __restrict__ ids, const float* __restrict__ emb,
                        const float* __restrict__ h, const float* __restrict__ W_ih,
                        const float* __restrict__ W_hh, const float* __restrict__ b_ih,
                        const float* __restrict__ b_hh) {
    extern __shared__ float xh[];    // [8][1536]
    const int tid = threadIdx.x;
    const int b0 = blockIdx.y * 8;
    for (int i = tid; i < 8 * E_; i += 256) {
        int bi = i >> 9, e = i & (E_ - 1);
        xh[bi * 1536 + e] = emb[(long)ids[b0 + bi] * E_ + e];
    }
    for (int i = tid; i < 8 * H_; i += 256) {
        int bi = i >> 10, e = i & (H_ - 1);
        xh[bi * 1536 + E_ + e] = h[(size_t)(b0 + bi) * H_ + e];
    }
    __syncthreads();
    const int col = blockIdx.x * 256 + tid;
    float bias = b_ih[col] + b_hh[col];
    float acc[8];
    #pragma unroll
    for (int bi = 0; bi < 8; bi++) acc[bi] = bias;
    for (int e = 0; e < 1536; e++) {
        float w = (e < E_) ? W_ih[(size_t)e * G4H + col]
                           : W_hh[(size_t)(e - E_) * G4H + col];
        #pragma unroll
        for (int bi = 0; bi < 8; bi++)
            acc[bi] = fmaf(xh[bi * 1536 + e], w, acc[bi]);
    }
    #pragma unroll
    for (int bi = 0; bi < 8; bi++)
        g_scratch[OFF_GATES + (size_t)(b0 + bi) * G4H + col] = acc[bi];
}

// ---------------------------------------------------------------------------
// LSTM elementwise (gate order i, f, g, o)
// ---------------------------------------------------------------------------
__global__ void lstm_k(const float* __restrict__ c_in,
                       float* __restrict__ h_t, float* __restrict__ c_t) {
    int idx = blockIdx.x * 256 + threadIdx.x;
    int b = idx >> 10, j = idx & 1023;
    const float* g = g_scratch + OFF_GATES + (size_t)b * G4H;
    float ig = sigmoidf_(g[j]);
    float fg = sigmoidf_(g[H_ + j]);
    float gg = tanhf(g[2 * H_ + j]);
    float og = sigmoidf_(g[3 * H_ + j]);
    float ct = fg * c_in[idx] + ig * gg;
    c_t[idx] = ct;
    h_t[idx] = og * tanhf(ct);
}

// ---------------------------------------------------------------------------
// Small-M GEMM, 8 batch rows per CTA (8x weight-traffic reduction vs 1-row):
// grid (N/256, M/8), block 256, smem = 8*K floats.
// C[m0+bi, col] (+)= sum_k A[m0+bi, k] * Bm[k, col]
// ---------------------------------------------------------------------------
__global__ void smallm8_k(const float* __restrict__ A, const float* __restrict__ Bm,
                          long Coff, int N, int K, int accumulate) {
    extern __shared__ float As[];   // [8][K]
    float* C = g_scratch + Coff;
    const int tid = threadIdx.x;
    const int m0 = blockIdx.y * 8;
    const int kv4 = K >> 2;
    for (int i = tid; i < 8 * kv4; i += 256) {
        int r = i / kv4, c4 = i - r * kv4;
        ((float4*)As)[i] =
            ((const float4*)(A + (size_t)(m0 + r) * K))[c4];
    }
    __syncthreads();
    int col = blockIdx.x * 256 + tid;
    float acc[8];
    #pragma unroll
    for (int bi = 0; bi < 8; bi++)
        acc[bi] = accumulate ? C[(size_t)(m0 + bi) * N + col] : 0.0f;
    #pragma unroll 4
    for (int kk = 0; kk < K; kk++) {
        float w = Bm[(size_t)kk * N + col];
        #pragma unroll
        for (int bi = 0; bi < 8; bi++)
            acc[bi] = fmaf(As[bi * K + kk], w, acc[bi]);
    }
    #pragma unroll
    for (int bi = 0; bi < 8; bi++)
        C[(size_t)(m0 + bi) * N + col] = acc[bi];
}

// ---------------------------------------------------------------------------
// TF32 GEMM, 128x128 tile, 4-stage cp.async, 2 CTAs/SM (proven config)
// ---------------------------------------------------------------------------
constexpr int CA_ASTRIDE = 20;
constexpr int CA_ASZ = 128 * CA_ASTRIDE;
constexpr int CA_BSZ = 16 * 128;
constexpr int CA_STAGES = 4;
constexpr int CA_SMEM_BYTES = CA_STAGES * (CA_ASZ + CA_BSZ) * 4;   // 73728

__global__ __launch_bounds__(256, 2) void tgemm_ca_k(
    const float* __restrict__ Ap, long Aoff,
    const float* __restrict__ Bm, int ldb,
    long Coff, int ldc,
    int M, int N, int K,
    const float* __restrict__ bias,
    int useRowAdd, long rowAddOff, int rowDiv,
    int doTanh,
    const float* __restrict__ dotW, long dotOff) {

    extern __shared__ float smem[];
    float* Abase = smem;
    float* Bbase = smem + CA_STAGES * CA_ASZ;

    const float* A = Ap ? Ap : (const float*)g_scratch + Aoff;

    const int tid  = threadIdx.x;
    const int wid  = tid >> 5;
    const int lane = tid & 31;
    const int warp_m = wid & 1;
    const int warp_n = wid >> 1;
    const int g   = lane >> 2;
    const int tig = lane & 3;

    const int bm = blockIdx.y * 128;
    const int bn = blockIdx.x * 128;
    const int nsteps = K >> 4;

    float acc[4][4][4];
    #pragma unroll
    for (int i = 0; i < 4; i++)
        #pragma unroll
        for (int j = 0; j < 4; j++)
            #pragma unroll
            for (int r = 0; r < 4; r++) acc[i][j][r] = 0.0f;

    const int aRow0 = tid >> 2;
    const int aC    = (tid & 3) * 4;
    const int bK0   = tid >> 5;
    const int bCn   = tid & 31;

    auto issue = [&](int buf, int kstep) {
        if (kstep < nsteps) {
            const int k0 = kstep << 4;
            float* Ad = Abase + buf * CA_ASZ;
            float* Bd = Bbase + buf * CA_BSZ;
            #pragma unroll
            for (int it = 0; it < 2; it++) {
                int row = aRow0 + it * 64;
                int rg = bm + row;
                int ok = rg < M;
                int rc = ok ? rg : (M - 1);
                cp_async16(smem_u32(Ad + row * CA_ASTRIDE + aC),
                           A + (size_t)rc * K + k0 + aC, ok ? 16 : 0);
            }
            #pragma unroll
            for (int it = 0; it < 2; it++) {
                int kr = bK0 + it * 8;
                uint32_t grp = (uint32_t)(bCn >> 1) ^ (uint32_t)(kr & 3);
                cp_async16(smem_u32(Bd + kr * 128 + grp * 8 + (bCn & 1) * 4),
                           Bm + (size_t)(k0 + kr) * ldb + bn + bCn * 4, 16);
            }
        }
        asm volatile("cp.async.commit_group;\n" ::: "memory");
    };

    int bcol[4];
    #pragma unroll
    for (int nti = 0; nti < 4; nti++)
        bcol[nti] = g + 8 * ((warp_n * 4 + nti) ^ tig);
    const int am0 = (warp_m * 64 + g) * CA_ASTRIDE;

    auto compute = [&](int buf) {
        const float* At = Abase + buf * CA_ASZ;
        const float* Bt = Bbase + buf * CA_BSZ;
        #pragma unroll
        for (int kt = 0; kt < 2; kt++) {
            const int k0 = kt * 8 + tig;
            float b0[4], b1[4];
            #pragma unroll
            for (int nti = 0; nti < 4; nti++) {
                b0[nti] = Bt[k0 * 128 + bcol[nti]];
                b1[nti] = Bt[(k0 + 4) * 128 + bcol[nti]];
            }
            #pragma unroll
            for (int mti = 0; mti < 4; mti++) {
                const float* Ar = At + am0 + mti * 16 * CA_ASTRIDE;
                float a0 = Ar[k0];
                float a1 = Ar[8 * CA_ASTRIDE + k0];
                float a2 = Ar[k0 + 4];
                float a3 = Ar[8 * CA_ASTRIDE + k0 + 4];
                #pragma unroll
                for (int nti = 0; nti < 4; nti++) {
                    asm volatile(
                        "mma.sync.aligned.m16n8k8.row.col.f32.tf32.tf32.f32 "
                        "{%0,%1,%2,%3}, {%4,%5,%6,%7}, {%8,%9}, {%0,%1,%2,%3};"
                        : "+f"(acc[mti][nti][0]), "+f"(acc[mti][nti][1]),
                          "+f"(acc[mti][nti][2]), "+f"(acc[mti][nti][3])
                        : "r"(__float_as_uint(a0)), "r"(__float_as_uint(a1)),
                          "r"(__float_as_uint(a2)), "r"(__float_as_uint(a3)),
                          "r"(__float_as_uint(b0[nti])), "r"(__float_as_uint(b1[nti])));
                }
            }
        }
    };

    issue(0, 0);
    issue(1, 1);
    issue(2, 2);

    #pragma unroll 4
    for (int s = 0; s < nsteps; s++) {
        asm volatile("cp.async.wait_group 2;\n" ::: "memory");
        __syncthreads();
        int nb = s + 3;
        issue(nb & 3, nb);
        compute(s & 3);
    }

    if (dotW) {
        float wv[4][2], bv[4][2];
        #pragma unroll
        for (int nti = 0; nti < 4; nti++)
            #pragma unroll
            for (int b2 = 0; b2 < 2; b2++) {
                int col = bn + warp_n * 32 + nti * 8 + tig * 2 + b2;
                wv[nti][b2] = dotW[col];
                bv[nti][b2] = bias ? bias[col] : 0.0f;
            }
        float part[4][2];
        #pragma unroll
        for (int i = 0; i < 4; i++) { part[i][0] = 0.f; part[i][1] = 0.f; }
        #pragma unroll
        for (int mti = 0; mti < 4; mti++)
            #pragma unroll
            for (int r = 0; r < 4; r++) {
                int rh = r >> 1;
                int cb = r & 1;
                #pragma unroll
                for (int nti = 0; nti < 4; nti++) {
                    float v = acc[mti][nti][r] + bv[nti][cb];
                    if (doTanh) v = tanhf(v);
                    part[mti][rh] = fmaf(v, wv[nti][cb], part[mti][rh]);
                }
            }
        #pragma unroll
        for (int i = 0; i < 4; i++) {
            #pragma unroll
            for (int rh = 0; rh < 2; rh++) {
                part[i][rh] += __shfl_xor_sync(0xffffffffu, part[i][rh], 1);
                part[i][rh] += __shfl_xor_sync(0xffffffffu, part[i][rh], 2);
            }
        }
        if (tig == 0) {
            float* buf = g_scratch + dotOff +
                         (size_t)(blockIdx.x * 4 + warp_n) * M;
            #pragma unroll
            for (int mti = 0; mti < 4; mti++)
                #pragma unroll
                for (int rh = 0; rh < 2; rh++) {
                    int row = bm + warp_m * 64 + mti * 16 + g + rh * 8;
                    if (row < M) buf[row] = part[mti][rh];
                }
        }
        return;
    }

    float* Co = g_scratch + Coff;
    const float* raB = useRowAdd ? (const float*)g_scratch + rowAddOff : nullptr;
    #pragma unroll
    for (int mti = 0; mti < 4; mti++) {
        #pragma unroll
        for (int r = 0; r < 4; r++) {
            int row = bm + warp_m * 64 + mti * 16 + g + ((r >= 2) ? 8 : 0);
            if (row >= M) continue;
            const float* ra = raB ? raB + (size_t)(row / rowDiv) * N : nullptr;
            #pragma unroll
            for (int nti = 0; nti < 4; nti++) {
                int col = bn + warp_n * 32 + nti * 8 + tig * 2 + (r & 1);
                float v = acc[mti][nti][r];
                if (bias) v += bias[col];
                if (ra) v += ra[col];
                if (doTanh) v = tanhf(v);
                Co[(size_t)row * ldc + col] = v;
            }
        }
    }
}

// ---------------------------------------------------------------------------
// reduce_k: out[row] = sum_{i<P} buf[i*M + row] + b[0]
// ---------------------------------------------------------------------------
__global__ void reduce_k(long bufOff, long outOff, int M, int P,
                         const float* __restrict__ bptr) {
    int row = blockIdx.x * 256 + threadIdx.x;
    if (row >= M) return;
    const float* buf = (const float*)g_scratch + bufOff;
    float s = bptr[0];
    for (int i = 0; i < P; i++) s += buf[(size_t)i * M + row];
    g_scratch[outOff + row] = s;
}

// ---------------------------------------------------------------------------
// Vocab GEMM half: y[64, V] (+)= A[64, :1024] @ Bm[1024, V] (+bias)(+vk)
// ---------------------------------------------------------------------------
constexpr int VG_ASTRIDE = 20;
constexpr int VG_ASZ = 64 * VG_ASTRIDE;
constexpr int VG_BSZ = 16 * 256;
constexpr int VG_STAGES = 4;
constexpr int VG_SMEM_BYTES = VG_STAGES * (VG_ASZ + VG_BSZ) * 4;

__global__ __launch_bounds__(256, 2) void vgemm_k(
    const float* __restrict__ Bm,
    const float* __restrict__ bias,
    float* __restrict__ y,
    const float* __restrict__ Aopt, long Aoff, int lda,
    int nsteps, int addTo, int useVk) {

    extern __shared__ float smem[];
    float* Abase = smem;
    float* Bbase = smem + VG_STAGES * VG_ASZ;

    const float* A = Aopt ? Aopt : (const float*)g_scratch + Aoff;

    const int tid  = threadIdx.x;
    const int wid  = tid >> 5;
    const int lane = tid & 31;
    const int g    = lane >> 2;
    const int tig  = lane & 3;

    const int bn = blockIdx.x * 256;

    float acc[4][4][4];
    #pragma unroll
    for (int i = 0; i < 4; i++)
        #pragma unroll
        for (int j = 0; j < 4; j++)
            #pragma unroll
            for (int r = 0; r < 4; r++) acc[i][j][r] = 0.0f;

    const int aRow = tid >> 2;
    const int aC   = (tid & 3) * 4;
    const int nCol = bn + tid;
    const int colOk = (nCol < V_) ? 4 : 0;
    const int nColC = (nCol < V_) ? nCol : (V_ - 1);

    auto issue = [&](int buf, int kstep) {
        if (kstep < nsteps) {
            const int k0 = kstep << 4;
            float* Ad = Abase + buf * VG_ASZ;
            float* Bd = Bbase + buf * VG_BSZ;
            cp_async16(smem_u32(Ad + aRow * VG_ASTRIDE + aC),
                       A + (size_t)aRow * lda + k0 + aC, 16);
            const float* src = Bm + (size_t)k0 * V_ + nColC;
            #pragma unroll
            for (int it = 0; it < 16; it++) {
                uint32_t dpos = (uint32_t)it * 256
                              + (((uint32_t)(tid >> 3) ^ (uint32_t)(it & 3)) * 8)
                              + (uint32_t)(tid & 7);
                cp_async4(smem_u32(Bd + dpos), src + (size_t)it * V_, colOk);
            }
        }
        asm volatile("cp.async.commit_group;\n" ::: "memory");
    };

    int bcol[4];
    #pragma unroll
    for (int nti = 0; nti < 4; nti++)
        bcol[nti] = g + 8 * ((wid * 4 + nti) ^ tig);
    const int am0 = g * VG_ASTRIDE;

    auto compute = [&](int buf) {
        const float* At = Abase + buf * VG_ASZ;
        const float* Bt = Bbase + buf * VG_BSZ;
        #pragma unroll
        for (int kt = 0; kt < 2; kt++) {
            const int k0 = kt * 8 + tig;
            float b0[4], b1[4];
            #pragma unroll
            for (int nti = 0; nti < 4; nti++) {
                b0[nti] = Bt[k0 * 256 + bcol[nti]];
                b1[nti] = Bt[(k0 + 4) * 256 + bcol[nti]];
            }
            #pragma unroll
            for (int mti = 0; mti < 4; mti++) {
                const float* Ar = At + am0 + mti * 16 * VG_ASTRIDE;
                float a0 = Ar[k0];
                float a1 = Ar[8 * VG_ASTRIDE + k0];
                float a2 = Ar[k0 + 4];
                float a3 = Ar[8 * VG_ASTRIDE + k0 + 4];
                #pragma unroll
                for (int nti = 0; nti < 4; nti++) {
                    asm volatile(
                        "mma.sync.aligned.m16n8k8.row.col.f32.tf32.tf32.f32 "
                        "{%0,%1,%2,%3}, {%4,%5,%6,%7}, {%8,%9}, {%0,%1,%2,%3};"
                        : "+f"(acc[mti][nti][0]), "+f"(acc[mti][nti][1]),
                          "+f"(acc[mti][nti][2]), "+f"(acc[mti][nti][3])
                        : "r"(__float_as_uint(a0)), "r"(__float_as_uint(a1)),
                          "r"(__float_as_uint(a2)), "r"(__float_as_uint(a3)),
                          "r"(__float_as_uint(b0[nti])), "r"(__float_as_uint(b1[nti])));
                }
            }
        }
    };

    issue(0, 0);
    issue(1, 1);
    issue(2, 2);

    #pragma unroll 4
    for (int s = 0; s < nsteps; s++) {
        asm volatile("cp.async.wait_group 2;\n" ::: "memory");
        __syncthreads();
        int nb = s + 3;
        issue(nb & 3, nb);
        compute(s & 3);
    }

    #pragma unroll
    for (int mti = 0; mti < 4; mti++) {
        #pragma unroll
        for (int r = 0; r < 4; r++) {
            int row = mti * 16 + g + ((r >= 2) ? 8 : 0);
            #pragma unroll
            for (int nti = 0; nti < 4; nti++) {
                int col = bn + wid * 32 + nti * 8 + tig * 2 + (r & 1);
                if (col >= V_) continue;
                float v = acc[mti][nti][r];
                if (bias) v += bias[col];
                if (addTo) v += y[(size_t)row * V_ + col];
                if (useVk) {
                    int kc = col - (V_ - KV_);
                    if (kc >= 0) v += g_scratch[OFF_VK + (size_t)row * KV_ + kc];
                }
                y[(size_t)row * V_ + col] = v;
            }
        }
    }
}

// ---------------------------------------------------------------------------
// softmax over L=512
// ---------------------------------------------------------------------------
__global__ void softmax_k() {
    __shared__ float red[32];
    float* row = g_scratch + OFF_SC + (size_t)blockIdx.x * L_;
    int tid = threadIdx.x;
    float v0 = row[tid], v1 = row[tid + 256];
    float m = blockReduceMax(fmaxf(v0, v1), red, tid);
    float e0 = expf(v0 - m), e1 = expf(v1 - m);
    float s = blockReduceSum(e0 + e1, red, tid);
    float inv = 1.0f / s;
    row[tid] = e0 * inv;
    row[tid + 256] = e1 * inv;
}

// ---------------------------------------------------------------------------
// h_ctx[b, col] = sum_l a[b,l] * enc[b,l,col]
// ---------------------------------------------------------------------------
__global__ void ctx_k(const float* __restrict__ enc) {
    __shared__ float as[L_];
    int b = blockIdx.y, tid = threadIdx.x;
    for (int i = tid; i < L_; i += 256) as[i] = g_scratch[OFF_SC + (size_t)b * L_ + i];
    __syncthreads();
    int col = blockIdx.x * 256 + tid;
    const float* ep = enc + (size_t)b * L_ * H_ + col;
    float acc = 0.f;
    #pragma unroll 4
    for (int l = 0; l < L_; l++) acc = fmaf(as[l], ep[(size_t)l * H_], acc);
    g_scratch[OFF_HCTX + (size_t)b * H_ + col] = acc;
}

// ---------------------------------------------------------------------------
// uk1[b*KV+kv, e4] = tanh(bpart[b] + kpart[kv] + kb1), float4 per thread
// ---------------------------------------------------------------------------
__global__ void uk1_k(const float* __restrict__ kb1) {
    size_t idx = (size_t)blockIdx.x * 256 + threadIdx.x;
    int e4 = (int)(idx & 127) * 4;
    size_t r = idx >> 7;
    int b = (int)(r / KV_);
    int kv = (int)(r - (size_t)b * KV_);
    float4 bp = *(const float4*)(g_scratch + OFF_BPART + (size_t)b * E_ + e4);
    float4 kp = *(const float4*)(g_scratch + OFF_KPART + (size_t)kv * E_ + e4);
    float4 kb = *(const float4*)(kb1 + e4);
    float4 o;
    o.x = tanhf(bp.x + kp.x + kb.x);
    o.y = tanhf(bp.y + kp.y + kb.y);
    o.z = tanhf(bp.z + kp.z + kb.z);
    o.w = tanhf(bp.w + kp.w + kb.w);
    *(float4*)(g_scratch + OFF_UK1 + r * E_ + e4) = o;
}

// ---------------------------------------------------------------------------
// Parallel log-softmax, 3 phases.
// ---------------------------------------------------------------------------
constexpr int LSM_CHUNK = (V_ + 7) / 8;

__global__ void lsm1_k(const float* __restrict__ y) {
    __shared__ float red[32];
    int row = blockIdx.y, chunk = blockIdx.x, tid = threadIdx.x;
    int start = chunk * LSM_CHUNK;
    int end = min(start + LSM_CHUNK, V_);
    const float* r = y + (size_t)row * V_;
    float m = -INFINITY;
    for (int i = start + tid; i < end; i += 256) m = fmaxf(m, r[i]);
    m = blockReduceMax(m, red, tid);
    float s = 0.f;
    for (int i = start + tid; i < end; i += 256) s += expf(r[i] - m);
    s = blockReduceSum(s, red, tid);
    if (tid == 0) {
        g_scratch[OFF_LSM + (row * 8 + chunk) * 2]     = m;
        g_scratch[OFF_LSM + (row * 8 + chunk) * 2 + 1] = s;
    }
}

__global__ void lsm2_k() {
    int row = threadIdx.x;
    float M = -INFINITY;
    #pragma unroll
    for (int i = 0; i < 8; i++)
        M = fmaxf(M, g_scratch[OFF_LSM + (row * 8 + i) * 2]);
    float S = 0.f;
    #pragma unroll
    for (int i = 0; i < 8; i++)
        S += g_scratch[OFF_LSM + (row * 8 + i) * 2 + 1] *
             expf(g_scratch[OFF_LSM + (row * 8 + i) * 2] - M);
    g_scratch[OFF_LSM + 1024 + row] = M + logf(S);
}

__global__ void lsm3_k(float* __restrict__ y) {
    int row = blockIdx.y;
    int base = blockIdx.x * 1024;
    float lse = g_scratch[OFF_LSM + 1024 + row];
    float* r = y + (size_t)row * V_;
    for (int i = base + threadIdx.x; i < min(base + 1024, V_); i += 256)
        r[i] -= lse;
}

// ---------------------------------------------------------------------------
// Launch — multi-stream fork/join inside graph capture
// ---------------------------------------------------------------------------
extern "C" void kernel_launch(void* const* d_in, const int* in_sizes, int n_in,
                              void* d_out, int out_size) {
    const int*   ids  = (const int*)d_in[0];
    const float* h    = (const float*)d_in[1];
    const float* c    = (const float*)d_in[2];
    const float* k    = (const float*)d_in[3];
    const float* ctxv = (const float*)d_in[4];
    const float* enc  = (const float*)d_in[5];
    const float* emb  = (const float*)d_in[6];
    const float* W_ih = (const float*)d_in[7];
    const float* W_hh = (const float*)d_in[8];
    const float* b_ih = (const float*)d_in[9];
    const float* b_hh = (const float*)d_in[10];
    const float* aW1  = (const float*)d_in[11];
    const float* ab1  = (const float*)d_in[12];
    const float* aW2  = (const float*)d_in[13];
    const float* ab2  = (const float*)d_in[14];
    const float* aW3  = (const float*)d_in[15];
    const float* ab3  = (const float*)d_in[16];
    const float* kW1  = (const float*)d_in[17];
    const float* kb1  = (const float*)d_in[18];
    const float* kW2  = (const float*)d_in[19];
    const float* kb2  = (const float*)d_in[20];
    const float* kW3  = (const float*)d_in[21];
    const float* kb3  = (const float*)d_in[22];
    const float* alW  = (const float*)d_in[23];
    const float* alb  = (const float*)d_in[24];

    float* y   = (float*)d_out;
    float* h_t = y + (size_t)B_ * V_;
    float* c_t = h_t + (size_t)B_ * H_;

    static cudaStream_t sK = nullptr, sV = nullptr;
    static cudaEvent_t evRoot = nullptr, evH = nullptr,
                       evVK = nullptr, evP1 = nullptr;
    if (!sK) {
        cudaStreamCreateWithFlags(&sK, cudaStreamNonBlocking);
        cudaStreamCreateWithFlags(&sV, cudaStreamNonBlocking);
        cudaEventCreateWithFlags(&evRoot, cudaEventDisableTiming);
        cudaEventCreateWithFlags(&evH,    cudaEventDisableTiming);
        cudaEventCreateWithFlags(&evVK,   cudaEventDisableTiming);
        cudaEventCreateWithFlags(&evP1,   cudaEventDisableTiming);
        cudaFuncSetAttribute(tgemm_ca_k, cudaFuncAttributeMaxDynamicSharedMemorySize,
                             CA_SMEM_BYTES);
        cudaFuncSetAttribute(vgemm_k, cudaFuncAttributeMaxDynamicSharedMemorySize,
                             VG_SMEM_BYTES);
        cudaFuncSetAttribute(gates_k, cudaFuncAttributeMaxDynamicSharedMemorySize,
                             8 * 1536 * (int)sizeof(float));
        cudaFuncSetAttribute(smallm8_k, cudaFuncAttributeMaxDynamicSharedMemorySize,
                             8 * H_ * (int)sizeof(float));
    }

    // ---- fork ---------------------------------------------------------------
    cudaEventRecord(evRoot, 0);
    cudaStreamWaitEvent(sK, evRoot, 0);
    cudaStreamWaitEvent(sV, evRoot, 0);

    // stream K: LSTM-independent key-attention prep
    tgemm_ca_k<<<dim3(E_ / 128, (KV_ + 127) / 128), 256, CA_SMEM_BYTES, sK>>>(
        k, 0, kW1 + (size_t)2 * H_ * E_, E_, OFF_KPART, E_,
        KV_, E_, E_, nullptr, 0, 0, 1, 0, nullptr, 0);
    smallm8_k<<<dim3(E_ / 256, B_ / 8), 256, 8 * H_ * sizeof(float), sK>>>(
        ctxv, kW1, OFF_BPART, E_, H_, 0);

    // stream 0: LSTM
    gates_k<<<dim3(G4H / 256, B_ / 8), 256, 8 * 1536 * sizeof(float)>>>(
        ids, emb, h, W_ih, W_hh, b_ih, b_hh);
    lstm_k<<<(B_ * H_) / 256, 256>>>(c, h_t, c_t);
    cudaEventRecord(evH, 0);
    cudaStreamWaitEvent(sK, evH, 0);
    cudaStreamWaitEvent(sV, evH, 0);

    // stream V: vocab GEMM pass 1 (h_t half)
    vgemm_k<<<(V_ + 255) / 256, 256, VG_SMEM_BYTES, sV>>>(
        alW, alb, y, h_t, 0, H_, H_ / 16, 0, 0);
    cudaEventRecord(evP1, sV);

    // stream K: key-attention chain
    smallm8_k<<<dim3(E_ / 256, B_ / 8), 256, 8 * H_ * sizeof(float), sK>>>(
        h_t, kW1 + (size_t)H_ * E_, OFF_BPART, E_, H_, 1);
    uk1_k<<<(B_ * KV_ * E_ / 4) / 256, 256, 0, sK>>>(kb1);
    tgemm_ca_k<<<dim3(E_ / 128, (B_ * KV_) / 128), 256, CA_SMEM_BYTES, sK>>>(
        nullptr, OFF_UK1, kW2, E_, 0, 0,
        B_ * KV_, E_, E_, kb2, 0, 0, 1, 1, kW3, OFF_UK2);
    reduce_k<<<(B_ * KV_ + 255) / 256, 256, 0, sK>>>(OFF_UK2, OFF_VK, B_ * KV_, 16, kb3);
    cudaEventRecord(evVK, sK);

    // stream 0: additive attention chain
    smallm8_k<<<dim3(E_ / 256, B_ / 8), 256, 8 * H_ * sizeof(float)>>>(
        h_t, aW1 + (size_t)H_ * E_, OFF_HB, E_, H_, 0);
    tgemm_ca_k<<<dim3(E_ / 128, (B_ * L_) / 128), 256, CA_SMEM_BYTES>>>(
        enc, 0, aW1, E_, OFF_U1, E_,
        B_ * L_, E_, H_, ab1, 1, OFF_HB, L_, 1, nullptr, 0);
    tgemm_ca_k<<<dim3(E_ / 128, (B_ * L_) / 128), 256, CA_SMEM_BYTES>>>(
        nullptr, OFF_U1, aW2, E_, 0, 0,
        B_ * L_, E_, E_, ab2, 0, 0, 1, 1, aW3, OFF_U2);
    reduce_k<<<(B_ * L_) / 256, 256>>>(OFF_U2, OFF_SC, B_ * L_, 16, ab3);
    softmax_k<<<B_, 256>>>();
    ctx_k<<<dim3(H_ / 256, B_), 256>>>(enc);

    // join: vocab GEMM pass 2 (hctx half + vk, accumulate)
    cudaStreamWaitEvent(0, evVK, 0);
    cudaStreamWaitEvent(0, evP1, 0);
    vgemm_k<<<(V_ + 255) / 256, 256, VG_SMEM_BYTES>>>(
        alW + (size_t)H_ * V_, nullptr, y, nullptr, OFF_HCTX, H_, H_ / 16, 1, 1);

    // parallel log-softmax
    lsm1_k<<<dim3(8, B_), 256>>>(y);
    lsm2_k<<<1, B_>>>();
    lsm3_k<<<dim3((V_ + 1023) / 1024, B_), 256>>>(y);
}

// round 15
// speedup vs baseline: 1.1057x; 1.1057x over previous
#include <cuda_runtime.h>
#include <math.h>
#include <stdint.h>

// ---------------------------------------------------------------------------
// Problem constants
// ---------------------------------------------------------------------------
constexpr int B_  = 64;
constexpr int H_  = 1024;
constexpr int E_  = 512;
constexpr int V_  = 50257;
constexpr int KV_ = 1000;
constexpr int L_  = 512;
constexpr int G4H = 4 * H_;   // 4096

// ---------------------------------------------------------------------------
// Scratch arena
// ---------------------------------------------------------------------------
constexpr long OFF_GATES = 0;
constexpr long OFF_HB    = OFF_GATES + (long)B_ * G4H;
constexpr long OFF_U1    = OFF_HB    + (long)B_ * E_;
constexpr long OFF_U2    = OFF_U1    + (long)B_ * L_ * E_;   // attn dot partials
constexpr long OFF_SC    = OFF_U2    + (long)B_ * L_ * E_;
constexpr long OFF_HCTX  = OFF_SC    + (long)B_ * L_;
constexpr long OFF_KPART = OFF_HCTX  + (long)B_ * H_;
constexpr long OFF_BPART = OFF_KPART + (long)KV_ * E_;
constexpr long OFF_UK1   = OFF_BPART + (long)B_ * E_;        // bf16 paired (uses half)
constexpr long OFF_UK2   = OFF_UK1   + (long)B_ * KV_ * E_;  // key dot partials
constexpr long OFF_VK    = OFF_UK2   + (long)B_ * KV_ * E_;
constexpr long OFF_LSM   = OFF_VK    + (long)B_ * KV_;
constexpr long SCRATCH_TOTAL = OFF_LSM + 2048;

__device__ __align__(16) float g_scratch[SCRATCH_TOTAL];

// ---------------------------------------------------------------------------
// Helpers
// ---------------------------------------------------------------------------
static __device__ __forceinline__ float sigmoidf_(float x) {
    return 1.0f / (1.0f + expf(-x));
}

static __device__ __forceinline__ uint32_t smem_u32(const void* p) {
    return (uint32_t)__cvta_generic_to_shared(p);
}

static __device__ __forceinline__ void cp_async16(uint32_t dst, const void* src, int szBytes) {
    asm volatile("cp.async.cg.shared.global [%0], [%1], 16, %2;\n"
                 :: "r"(dst), "l"(src), "r"(szBytes) : "memory");
}

static __device__ __forceinline__ void cp_async4(uint32_t dst, const void* src, int szBytes) {
    asm volatile("cp.async.ca.shared.global [%0], [%1], 4, %2;\n"
                 :: "r"(dst), "l"(src), "r"(szBytes) : "memory");
}

static __device__ __forceinline__ float blockReduceMax(float v, float* red, int tid) {
    #pragma unroll
    for (int o = 16; o; o >>= 1) v = fmaxf(v, __shfl_xor_sync(0xffffffffu, v, o));
    if ((tid & 31) == 0) red[tid >> 5] = v;
    __syncthreads();
    int nw = blockDim.x >> 5;
    float r = red[0];
    for (int i = 1; i < nw; i++) r = fmaxf(r, red[i]);
    __syncthreads();
    return r;
}

static __device__ __forceinline__ float blockReduceSum(float v, float* red, int tid) {
    #pragma unroll
    for (int o = 16; o; o >>= 1) v += __shfl_xor_sync(0xffffffffu, v, o);
    if ((tid & 31) == 0) red[tid >> 5] = v;
    __syncthreads();
    int nw = blockDim.x >> 5;
    float r = red[0];
    for (int i = 1; i < nw; i++) r += red[i];
    __syncthreads();
    return r;
}

// ---------------------------------------------------------------------------
// LSTM gates
// ---------------------------------------------------------------------------
__global__ void gates_k(const int* __restrict__ ids, const float* __restrict__ emb,
                        const float* __restrict__ h, const float* __restrict__ W_ih,
                        const float* __restrict__ W_hh, const float* __restrict__ b_ih,
                        const float* __restrict__ b_hh) {
    extern __shared__ float xh[];    // [8][1536]
    const int tid = threadIdx.x;
    const int b0 = blockIdx.y * 8;
    for (int i = tid; i < 8 * E_; i += 256) {
        int bi = i >> 9, e = i & (E_ - 1);
        xh[bi * 1536 + e] = emb[(long)ids[b0 + bi] * E_ + e];
    }
    for (int i = tid; i < 8 * H_; i += 256) {
        int bi = i >> 10, e = i & (H_ - 1);
        xh[bi * 1536 + E_ + e] = h[(size_t)(b0 + bi) * H_ + e];
    }
    __syncthreads();
    const int col = blockIdx.x * 256 + tid;
    float bias = b_ih[col] + b_hh[col];
    float acc[8];
    #pragma unroll
    for (int bi = 0; bi < 8; bi++) acc[bi] = bias;
    for (int e = 0; e < 1536; e++) {
        float w = (e < E_) ? W_ih[(size_t)e * G4H + col]
                           : W_hh[(size_t)(e - E_) * G4H + col];
        #pragma unroll
        for (int bi = 0; bi < 8; bi++)
            acc[bi] = fmaf(xh[bi * 1536 + e], w, acc[bi]);
    }
    #pragma unroll
    for (int bi = 0; bi < 8; bi++)
        g_scratch[OFF_GATES + (size_t)(b0 + bi) * G4H + col] = acc[bi];
}

// ---------------------------------------------------------------------------
// LSTM elementwise (gate order i, f, g, o)
// ---------------------------------------------------------------------------
__global__ void lstm_k(const float* __restrict__ c_in,
                       float* __restrict__ h_t, float* __restrict__ c_t) {
    int idx = blockIdx.x * 256 + threadIdx.x;
    int b = idx >> 10, j = idx & 1023;
    const float* g = g_scratch + OFF_GATES + (size_t)b * G4H;
    float ig = sigmoidf_(g[j]);
    float fg = sigmoidf_(g[H_ + j]);
    float gg = tanhf(g[2 * H_ + j]);
    float og = sigmoidf_(g[3 * H_ + j]);
    float ct = fg * c_in[idx] + ig * gg;
    c_t[idx] = ct;
    h_t[idx] = og * tanhf(ct);
}

// ---------------------------------------------------------------------------
// Small-M GEMM (one row per blockIdx.y — weight panel is L2-resident)
// ---------------------------------------------------------------------------
__global__ void smallm_k(const float* __restrict__ A, const float* __restrict__ Bm,
                         long Coff, int N, int K, int accumulate) {
    extern __shared__ float As[];
    float* C = g_scratch + Coff;
    int m = blockIdx.y;
    for (int i = threadIdx.x; i < K; i += blockDim.x) As[i] = A[(size_t)m * K + i];
    __syncthreads();
    int col = blockIdx.x * blockDim.x + threadIdx.x;
    float acc = accumulate ? C[(size_t)m * N + col] : 0.0f;
    #pragma unroll 4
    for (int kk = 0; kk < K; kk++)
        acc = fmaf(As[kk], Bm[(size_t)kk * N + col], acc);
    C[(size_t)m * N + col] = acc;
}

// ---------------------------------------------------------------------------
// TF32 GEMM, 128x128 tile, 4-stage cp.async, 2 CTAs/SM (proven config)
// ---------------------------------------------------------------------------
constexpr int CA_ASTRIDE = 20;
constexpr int CA_ASZ = 128 * CA_ASTRIDE;
constexpr int CA_BSZ = 16 * 128;
constexpr int CA_STAGES = 4;
constexpr int CA_SMEM_BYTES = CA_STAGES * (CA_ASZ + CA_BSZ) * 4;   // 73728

__global__ __launch_bounds__(256, 2) void tgemm_ca_k(
    const float* __restrict__ Ap, long Aoff,
    const float* __restrict__ Bm, int ldb,
    long Coff, int ldc,
    int M, int N, int K,
    const float* __restrict__ bias,
    int useRowAdd, long rowAddOff, int rowDiv,
    int doTanh,
    const float* __restrict__ dotW, long dotOff) {

    extern __shared__ float smem[];
    float* Abase = smem;
    float* Bbase = smem + CA_STAGES * CA_ASZ;

    const float* A = Ap ? Ap : (const float*)g_scratch + Aoff;

    const int tid  = threadIdx.x;
    const int wid  = tid >> 5;
    const int lane = tid & 31;
    const int warp_m = wid & 1;
    const int warp_n = wid >> 1;
    const int g   = lane >> 2;
    const int tig = lane & 3;

    const int bm = blockIdx.y * 128;
    const int bn = blockIdx.x * 128;
    const int nsteps = K >> 4;

    float acc[4][4][4];
    #pragma unroll
    for (int i = 0; i < 4; i++)
        #pragma unroll
        for (int j = 0; j < 4; j++)
            #pragma unroll
            for (int r = 0; r < 4; r++) acc[i][j][r] = 0.0f;

    const int aRow0 = tid >> 2;
    const int aC    = (tid & 3) * 4;
    const int bK0   = tid >> 5;
    const int bCn   = tid & 31;

    auto issue = [&](int buf, int kstep) {
        if (kstep < nsteps) {
            const int k0 = kstep << 4;
            float* Ad = Abase + buf * CA_ASZ;
            float* Bd = Bbase + buf * CA_BSZ;
            #pragma unroll
            for (int it = 0; it < 2; it++) {
                int row = aRow0 + it * 64;
                int rg = bm + row;
                int ok = rg < M;
                int rc = ok ? rg : (M - 1);
                cp_async16(smem_u32(Ad + row * CA_ASTRIDE + aC),
                           A + (size_t)rc * K + k0 + aC, ok ? 16 : 0);
            }
            #pragma unroll
            for (int it = 0; it < 2; it++) {
                int kr = bK0 + it * 8;
                uint32_t grp = (uint32_t)(bCn >> 1) ^ (uint32_t)(kr & 3);
                cp_async16(smem_u32(Bd + kr * 128 + grp * 8 + (bCn & 1) * 4),
                           Bm + (size_t)(k0 + kr) * ldb + bn + bCn * 4, 16);
            }
        }
        asm volatile("cp.async.commit_group;\n" ::: "memory");
    };

    int bcol[4];
    #pragma unroll
    for (int nti = 0; nti < 4; nti++)
        bcol[nti] = g + 8 * ((warp_n * 4 + nti) ^ tig);
    const int am0 = (warp_m * 64 + g) * CA_ASTRIDE;

    auto compute = [&](int buf) {
        const float* At = Abase + buf * CA_ASZ;
        const float* Bt = Bbase + buf * CA_BSZ;
        #pragma unroll
        for (int kt = 0; kt < 2; kt++) {
            const int k0 = kt * 8 + tig;
            float b0[4], b1[4];
            #pragma unroll
            for (int nti = 0; nti < 4; nti++) {
                b0[nti] = Bt[k0 * 128 + bcol[nti]];
                b1[nti] = Bt[(k0 + 4) * 128 + bcol[nti]];
            }
            #pragma unroll
            for (int mti = 0; mti < 4; mti++) {
                const float* Ar = At + am0 + mti * 16 * CA_ASTRIDE;
                float a0 = Ar[k0];
                float a1 = Ar[8 * CA_ASTRIDE + k0];
                float a2 = Ar[k0 + 4];
                float a3 = Ar[8 * CA_ASTRIDE + k0 + 4];
                #pragma unroll
                for (int nti = 0; nti < 4; nti++) {
                    asm volatile(
                        "mma.sync.aligned.m16n8k8.row.col.f32.tf32.tf32.f32 "
                        "{%0,%1,%2,%3}, {%4,%5,%6,%7}, {%8,%9}, {%0,%1,%2,%3};"
                        : "+f"(acc[mti][nti][0]), "+f"(acc[mti][nti][1]),
                          "+f"(acc[mti][nti][2]), "+f"(acc[mti][nti][3])
                        : "r"(__float_as_uint(a0)), "r"(__float_as_uint(a1)),
                          "r"(__float_as_uint(a2)), "r"(__float_as_uint(a3)),
                          "r"(__float_as_uint(b0[nti])), "r"(__float_as_uint(b1[nti])));
                }
            }
        }
    };

    issue(0, 0);
    issue(1, 1);
    issue(2, 2);

    #pragma unroll 4
    for (int s = 0; s < nsteps; s++) {
        asm volatile("cp.async.wait_group 2;\n" ::: "memory");
        __syncthreads();
        int nb = s + 3;
        issue(nb & 3, nb);
        compute(s & 3);
    }

    if (dotW) {
        float wv[4][2], bv[4][2];
        #pragma unroll
        for (int nti = 0; nti < 4; nti++)
            #pragma unroll
            for (int b2 = 0; b2 < 2; b2++) {
                int col = bn + warp_n * 32 + nti * 8 + tig * 2 + b2;
                wv[nti][b2] = dotW[col];
                bv[nti][b2] = bias ? bias[col] : 0.0f;
            }
        float part[4][2];
        #pragma unroll
        for (int i = 0; i < 4; i++) { part[i][0] = 0.f; part[i][1] = 0.f; }
        #pragma unroll
        for (int mti = 0; mti < 4; mti++)
            #pragma unroll
            for (int r = 0; r < 4; r++) {
                int rh = r >> 1;
                int cb = r & 1;
                #pragma unroll
                for (int nti = 0; nti < 4; nti++) {
                    float v = acc[mti][nti][r] + bv[nti][cb];
                    if (doTanh) v = tanhf(v);
                    part[mti][rh] = fmaf(v, wv[nti][cb], part[mti][rh]);
                }
            }
        #pragma unroll
        for (int i = 0; i < 4; i++) {
            #pragma unroll
            for (int rh = 0; rh < 2; rh++) {
                part[i][rh] += __shfl_xor_sync(0xffffffffu, part[i][rh], 1);
                part[i][rh] += __shfl_xor_sync(0xffffffffu, part[i][rh], 2);
            }
        }
        if (tig == 0) {
            float* buf = g_scratch + dotOff +
                         (size_t)(blockIdx.x * 4 + warp_n) * M;
            #pragma unroll
            for (int mti = 0; mti < 4; mti++)
                #pragma unroll
                for (int rh = 0; rh < 2; rh++) {
                    int row = bm + warp_m * 64 + mti * 16 + g + rh * 8;
                    if (row < M) buf[row] = part[mti][rh];
                }
        }
        return;
    }

    float* Co = g_scratch + Coff;
    const float* raB = useRowAdd ? (const float*)g_scratch + rowAddOff : nullptr;
    #pragma unroll
    for (int mti = 0; mti < 4; mti++) {
        #pragma unroll
        for (int r = 0; r < 4; r++) {
            int row = bm + warp_m * 64 + mti * 16 + g + ((r >= 2) ? 8 : 0);
            if (row >= M) continue;
            const float* ra = raB ? raB + (size_t)(row / rowDiv) * N : nullptr;
            #pragma unroll
            for (int nti = 0; nti < 4; nti++) {
                int col = bn + warp_n * 32 + nti * 8 + tig * 2 + (r & 1);
                float v = acc[mti][nti][r];
                if (bias) v += bias[col];
                if (ra) v += ra[col];
                if (doTanh) v = tanhf(v);
                Co[(size_t)row * ldc + col] = v;
            }
        }
    }
}

// ---------------------------------------------------------------------------
// uk2 GEMM with bf16 A (paired layout from uk1_k): A[row][k] pairs (k, k+4)
// packed in one uint32; per kstep a row holds 8 u32 = [kt0: 4 u32][kt1: 4 u32].
// A smem: [stage][kt][128 rows][4 u32] (stride 4 -> g*4+tig spans all banks).
// B = kW2 fp32, same swizzled path as tgemm. tf32 mma; dot epilogue (kW3).
// M = 64000 (mult of 128), K = 512, N = 512.
// ---------------------------------------------------------------------------
constexpr int UA_ASZ = 1024;   // uint32 per A stage
constexpr int UA_SMEM_BYTES = CA_STAGES * (UA_ASZ + CA_BSZ) * 4;   // 49152

__global__ __launch_bounds__(256, 2) void tgemm_bf16a_k(
    const float* __restrict__ Bm,      // kW2 [512,512]
    const float* __restrict__ bias,    // kb2
    const float* __restrict__ dotW,    // kW3
    long dotOff) {

    extern __shared__ float smem[];
    uint32_t* Abase = (uint32_t*)smem;                 // 4 stages x 1024 u32
    float* Bbase = smem + CA_STAGES * UA_ASZ;          // 4 stages x 2048 f32

    const uint32_t* Ag = (const uint32_t*)(g_scratch + OFF_UK1);

    const int tid  = threadIdx.x;
    const int wid  = tid >> 5;
    const int lane = tid & 31;
    const int warp_m = wid & 1;
    const int warp_n = wid >> 1;
    const int g   = lane >> 2;
    const int tig = lane & 3;

    const int bm = blockIdx.y * 128;
    const int bn = blockIdx.x * 128;
    const int M = B_ * KV_;
    constexpr int nsteps = E_ >> 4;    // 32

    float acc[4][4][4];
    #pragma unroll
    for (int i = 0; i < 4; i++)
        #pragma unroll
        for (int j = 0; j < 4; j++)
            #pragma unroll
            for (int r = 0; r < 4; r++) acc[i][j][r] = 0.0f;

    const int aRow  = tid >> 1;        // 0..127
    const int aHalf = tid & 1;         // kt half
    const int bK0   = tid >> 5;
    const int bCn   = tid & 31;

    auto issue = [&](int buf, int kstep) {
        if (kstep < nsteps) {
            uint32_t* Ad = Abase + buf * UA_ASZ;
            float* Bd = Bbase + buf * CA_BSZ;
            cp_async16(smem_u32(Ad + aHalf * 512 + aRow * 4),
                       Ag + (size_t)(bm + aRow) * 256 + kstep * 8 + aHalf * 4, 16);
            const int k0 = kstep << 4;
            #pragma unroll
            for (int it = 0; it < 2; it++) {
                int kr = bK0 + it * 8;
                uint32_t grp = (uint32_t)(bCn >> 1) ^ (uint32_t)(kr & 3);
                cp_async16(smem_u32(Bd + kr * 128 + grp * 8 + (bCn & 1) * 4),
                           Bm + (size_t)(k0 + kr) * E_ + bn + bCn * 4, 16);
            }
        }
        asm volatile("cp.async.commit_group;\n" ::: "memory");
    };

    int bcol[4];
    #pragma unroll
    for (int nti = 0; nti < 4; nti++)
        bcol[nti] = g + 8 * ((warp_n * 4 + nti) ^ tig);

    auto compute = [&](int buf) {
        const uint32_t* At = Abase + buf * UA_ASZ;
        const float* Bt = Bbase + buf * CA_BSZ;
        #pragma unroll
        for (int kt = 0; kt < 2; kt++) {
            const int k0 = kt * 8 + tig;
            float b0[4], b1[4];
            #pragma unroll
            for (int nti = 0; nti < 4; nti++) {
                b0[nti] = Bt[k0 * 128 + bcol[nti]];
                b1[nti] = Bt[(k0 + 4) * 128 + bcol[nti]];
            }
            const uint32_t* Ak = At + kt * 512 + tig;
            #pragma unroll
            for (int mti = 0; mti < 4; mti++) {
                int row0 = warp_m * 64 + mti * 16 + g;
                uint32_t u0 = Ak[row0 * 4];
                uint32_t u1 = Ak[(row0 + 8) * 4];
                float a0 = __uint_as_float(u0 << 16);
                float a2 = __uint_as_float(u0 & 0xffff0000u);
                float a1 = __uint_as_float(u1 << 16);
                float a3 = __uint_as_float(u1 & 0xffff0000u);
                #pragma unroll
                for (int nti = 0; nti < 4; nti++) {
                    asm volatile(
                        "mma.sync.aligned.m16n8k8.row.col.f32.tf32.tf32.f32 "
                        "{%0,%1,%2,%3}, {%4,%5,%6,%7}, {%8,%9}, {%0,%1,%2,%3};"
                        : "+f"(acc[mti][nti][0]), "+f"(acc[mti][nti][1]),
                          "+f"(acc[mti][nti][2]), "+f"(acc[mti][nti][3])
                        : "r"(__float_as_uint(a0)), "r"(__float_as_uint(a1)),
                          "r"(__float_as_uint(a2)), "r"(__float_as_uint(a3)),
                          "r"(__float_as_uint(b0[nti])), "r"(__float_as_uint(b1[nti])));
                }
            }
        }
    };

    issue(0, 0);
    issue(1, 1);
    issue(2, 2);

    #pragma unroll 4
    for (int s = 0; s < nsteps; s++) {
        asm volatile("cp.async.wait_group 2;\n" ::: "memory");
        __syncthreads();
        int nb = s + 3;
        issue(nb & 3, nb);
        compute(s & 3);
    }

    // fused kW3 dot epilogue
    float wv[4][2], bv[4][2];
    #pragma unroll
    for (int nti = 0; nti < 4; nti++)
        #pragma unroll
        for (int b2 = 0; b2 < 2; b2++) {
            int col = bn + warp_n * 32 + nti * 8 + tig * 2 + b2;
            wv[nti][b2] = dotW[col];
            bv[nti][b2] = bias[col];
        }
    float part[4][2];
    #pragma unroll
    for (int i = 0; i < 4; i++) { part[i][0] = 0.f; part[i][1] = 0.f; }
    #pragma unroll
    for (int mti = 0; mti < 4; mti++)
        #pragma unroll
        for (int r = 0; r < 4; r++) {
            int rh = r >> 1;
            int cb = r & 1;
            #pragma unroll
            for (int nti = 0; nti < 4; nti++) {
                float v = tanhf(acc[mti][nti][r] + bv[nti][cb]);
                part[mti][rh] = fmaf(v, wv[nti][cb], part[mti][rh]);
            }
        }
    #pragma unroll
    for (int i = 0; i < 4; i++) {
        #pragma unroll
        for (int rh = 0; rh < 2; rh++) {
            part[i][rh] += __shfl_xor_sync(0xffffffffu, part[i][rh], 1);
            part[i][rh] += __shfl_xor_sync(0xffffffffu, part[i][rh], 2);
        }
    }
    if (tig == 0) {
        float* buf = g_scratch + dotOff + (size_t)(blockIdx.x * 4 + warp_n) * M;
        #pragma unroll
        for (int mti = 0; mti < 4; mti++)
            #pragma unroll
            for (int rh = 0; rh < 2; rh++) {
                int row = bm + warp_m * 64 + mti * 16 + g + rh * 8;
                buf[row] = part[mti][rh];
            }
    }
}

// ---------------------------------------------------------------------------
// reduce_k: out[row] = sum_{i<P} buf[i*M + row] + b[0]
// ---------------------------------------------------------------------------
__global__ void reduce_k(long bufOff, long outOff, int M, int P,
                         const float* __restrict__ bptr) {
    int row = blockIdx.x * 256 + threadIdx.x;
    if (row >= M) return;
    const float* buf = (const float*)g_scratch + bufOff;
    float s = bptr[0];
    for (int i = 0; i < P; i++) s += buf[(size_t)i * M + row];
    g_scratch[outOff + row] = s;
}

// ---------------------------------------------------------------------------
// Vocab GEMM half: y[64, V] (+)= A[64, :1024] @ Bm[1024, V] (+bias)(+vk)
// ---------------------------------------------------------------------------
constexpr int VG_ASTRIDE = 20;
constexpr int VG_ASZ = 64 * VG_ASTRIDE;
constexpr int VG_BSZ = 16 * 256;
constexpr int VG_STAGES = 4;
constexpr int VG_SMEM_BYTES = VG_STAGES * (VG_ASZ + VG_BSZ) * 4;

__global__ __launch_bounds__(256, 2) void vgemm_k(
    const float* __restrict__ Bm,
    const float* __restrict__ bias,
    float* __restrict__ y,
    const float* __restrict__ Aopt, long Aoff, int lda,
    int nsteps, int addTo, int useVk) {

    extern __shared__ float smem[];
    float* Abase = smem;
    float* Bbase = smem + VG_STAGES * VG_ASZ;

    const float* A = Aopt ? Aopt : (const float*)g_scratch + Aoff;

    const int tid  = threadIdx.x;
    const int wid  = tid >> 5;
    const int lane = tid & 31;
    const int g    = lane >> 2;
    const int tig  = lane & 3;

    const int bn = blockIdx.x * 256;

    float acc[4][4][4];
    #pragma unroll
    for (int i = 0; i < 4; i++)
        #pragma unroll
        for (int j = 0; j < 4; j++)
            #pragma unroll
            for (int r = 0; r < 4; r++) acc[i][j][r] = 0.0f;

    const int aRow = tid >> 2;
    const int aC   = (tid & 3) * 4;
    const int nCol = bn + tid;
    const int colOk = (nCol < V_) ? 4 : 0;
    const int nColC = (nCol < V_) ? nCol : (V_ - 1);

    auto issue = [&](int buf, int kstep) {
        if (kstep < nsteps) {
            const int k0 = kstep << 4;
            float* Ad = Abase + buf * VG_ASZ;
            float* Bd = Bbase + buf * VG_BSZ;
            cp_async16(smem_u32(Ad + aRow * VG_ASTRIDE + aC),
                       A + (size_t)aRow * lda + k0 + aC, 16);
            const float* src = Bm + (size_t)k0 * V_ + nColC;
            #pragma unroll
            for (int it = 0; it < 16; it++) {
                uint32_t dpos = (uint32_t)it * 256
                              + (((uint32_t)(tid >> 3) ^ (uint32_t)(it & 3)) * 8)
                              + (uint32_t)(tid & 7);
                cp_async4(smem_u32(Bd + dpos), src + (size_t)it * V_, colOk);
            }
        }
        asm volatile("cp.async.commit_group;\n" ::: "memory");
    };

    int bcol[4];
    #pragma unroll
    for (int nti = 0; nti < 4; nti++)
        bcol[nti] = g + 8 * ((wid * 4 + nti) ^ tig);
    const int am0 = g * VG_ASTRIDE;

    auto compute = [&](int buf) {
        const float* At = Abase + buf * VG_ASZ;
        const float* Bt = Bbase + buf * VG_BSZ;
        #pragma unroll
        for (int kt = 0; kt < 2; kt++) {
            const int k0 = kt * 8 + tig;
            float b0[4], b1[4];
            #pragma unroll
            for (int nti = 0; nti < 4; nti++) {
                b0[nti] = Bt[k0 * 256 + bcol[nti]];
                b1[nti] = Bt[(k0 + 4) * 256 + bcol[nti]];
            }
            #pragma unroll
            for (int mti = 0; mti < 4; mti++) {
                const float* Ar = At + am0 + mti * 16 * VG_ASTRIDE;
                float a0 = Ar[k0];
                float a1 = Ar[8 * VG_ASTRIDE + k0];
                float a2 = Ar[k0 + 4];
                float a3 = Ar[8 * VG_ASTRIDE + k0 + 4];
                #pragma unroll
                for (int nti = 0; nti < 4; nti++) {
                    asm volatile(
                        "mma.sync.aligned.m16n8k8.row.col.f32.tf32.tf32.f32 "
                        "{%0,%1,%2,%3}, {%4,%5,%6,%7}, {%8,%9}, {%0,%1,%2,%3};"
                        : "+f"(acc[mti][nti][0]), "+f"(acc[mti][nti][1]),
                          "+f"(acc[mti][nti][2]), "+f"(acc[mti][nti][3])
                        : "r"(__float_as_uint(a0)), "r"(__float_as_uint(a1)),
                          "r"(__float_as_uint(a2)), "r"(__float_as_uint(a3)),
                          "r"(__float_as_uint(b0[nti])), "r"(__float_as_uint(b1[nti])));
                }
            }
        }
    };

    issue(0, 0);
    issue(1, 1);
    issue(2, 2);

    #pragma unroll 4
    for (int s = 0; s < nsteps; s++) {
        asm volatile("cp.async.wait_group 2;\n" ::: "memory");
        __syncthreads();
        int nb = s + 3;
        issue(nb & 3, nb);
        compute(s & 3);
    }

    #pragma unroll
    for (int mti = 0; mti < 4; mti++) {
        #pragma unroll
        for (int r = 0; r < 4; r++) {
            int row = mti * 16 + g + ((r >= 2) ? 8 : 0);
            #pragma unroll
            for (int nti = 0; nti < 4; nti++) {
                int col = bn + wid * 32 + nti * 8 + tig * 2 + (r & 1);
                if (col >= V_) continue;
                float v = acc[mti][nti][r];
                if (bias) v += bias[col];
                if (addTo) v += y[(size_t)row * V_ + col];
                if (useVk) {
                    int kc = col - (V_ - KV_);
                    if (kc >= 0) v += g_scratch[OFF_VK + (size_t)row * KV_ + kc];
                }
                y[(size_t)row * V_ + col] = v;
            }
        }
    }
}

// ---------------------------------------------------------------------------
// softmax over L=512
// ---------------------------------------------------------------------------
__global__ void softmax_k() {
    __shared__ float red[32];
    float* row = g_scratch + OFF_SC + (size_t)blockIdx.x * L_;
    int tid = threadIdx.x;
    float v0 = row[tid], v1 = row[tid + 256];
    float m = blockReduceMax(fmaxf(v0, v1), red, tid);
    float e0 = expf(v0 - m), e1 = expf(v1 - m);
    float s = blockReduceSum(e0 + e1, red, tid);
    float inv = 1.0f / s;
    row[tid] = e0 * inv;
    row[tid + 256] = e1 * inv;
}

// ---------------------------------------------------------------------------
// h_ctx[b, col] = sum_l a[b,l] * enc[b,l,col]
// ---------------------------------------------------------------------------
__global__ void ctx_k(const float* __restrict__ enc) {
    __shared__ float as[L_];
    int b = blockIdx.y, tid = threadIdx.x;
    for (int i = tid; i < L_; i += 256) as[i] = g_scratch[OFF_SC + (size_t)b * L_ + i];
    __syncthreads();
    int col = blockIdx.x * 256 + tid;
    const float* ep = enc + (size_t)b * L_ * H_ + col;
    float acc = 0.f;
    #pragma unroll 4
    for (int l = 0; l < L_; l++) acc = fmaf(as[l], ep[(size_t)l * H_], acc);
    g_scratch[OFF_HCTX + (size_t)b * H_ + col] = acc;
}

// ---------------------------------------------------------------------------
// uk1: UK1 (bf16, paired) [b*KV+kv][k] = tanh(bpart+kpart+kb1)
// Each thread: one 8-element group; writes 4 u32 = pairs (j, j+4).
// ---------------------------------------------------------------------------
__global__ void uk1_k(const float* __restrict__ kb1) {
    size_t idx = (size_t)blockIdx.x * 256 + threadIdx.x;   // B*KV*64 groups
    int g8 = (int)(idx & 63);
    size_t r = idx >> 6;
    int b = (int)(r / KV_);
    int kv = (int)(r - (size_t)b * KV_);
    int e = g8 * 8;
    const float* bp = g_scratch + OFF_BPART + (size_t)b * E_ + e;
    const float* kp = g_scratch + OFF_KPART + (size_t)kv * E_ + e;
    float4 b0 = *(const float4*)bp,  b1 = *(const float4*)(bp + 4);
    float4 k0 = *(const float4*)kp,  k1 = *(const float4*)(kp + 4);
    float4 c0 = *(const float4*)(kb1 + e), c1 = *(const float4*)(kb1 + e + 4);
    float t[8];
    t[0] = tanhf(b0.x + k0.x + c0.x);
    t[1] = tanhf(b0.y + k0.y + c0.y);
    t[2] = tanhf(b0.z + k0.z + c0.z);
    t[3] = tanhf(b0.w + k0.w + c0.w);
    t[4] = tanhf(b1.x + k1.x + c1.x);
    t[5] = tanhf(b1.y + k1.y + c1.y);
    t[6] = tanhf(b1.z + k1.z + c1.z);
    t[7] = tanhf(b1.w + k1.w + c1.w);
    uint32_t u[4];
    #pragma unroll
    for (int j = 0; j < 4; j++)
        asm("cvt.rn.bf16x2.f32 %0, %1, %2;"
            : "=r"(u[j]) : "f"(t[j + 4]), "f"(t[j]));   // hi = t[j+4], lo = t[j]
    uint4* dst = (uint4*)((uint32_t*)(g_scratch + OFF_UK1) + r * 256 + g8 * 4);
    *dst = make_uint4(u[0], u[1], u[2], u[3]);
}

// ---------------------------------------------------------------------------
// Parallel log-softmax, 3 phases.
// ---------------------------------------------------------------------------
constexpr int LSM_CHUNK = (V_ + 7) / 8;

__global__ void lsm1_k(const float* __restrict__ y) {
    __shared__ float red[32];
    int row = blockIdx.y, chunk = blockIdx.x, tid = threadIdx.x;
    int start = chunk * LSM_CHUNK;
    int end = min(start + LSM_CHUNK, V_);
    const float* r = y + (size_t)row * V_;
    float m = -INFINITY;
    for (int i = start + tid; i < end; i += 256) m = fmaxf(m, r[i]);
    m = blockReduceMax(m, red, tid);
    float s = 0.f;
    for (int i = start + tid; i < end; i += 256) s += expf(r[i] - m);
    s = blockReduceSum(s, red, tid);
    if (tid == 0) {
        g_scratch[OFF_LSM + (row * 8 + chunk) * 2]     = m;
        g_scratch[OFF_LSM + (row * 8 + chunk) * 2 + 1] = s;
    }
}

__global__ void lsm2_k() {
    int row = threadIdx.x;
    float M = -INFINITY;
    #pragma unroll
    for (int i = 0; i < 8; i++)
        M = fmaxf(M, g_scratch[OFF_LSM + (row * 8 + i) * 2]);
    float S = 0.f;
    #pragma unroll
    for (int i = 0; i < 8; i++)
        S += g_scratch[OFF_LSM + (row * 8 + i) * 2 + 1] *
             expf(g_scratch[OFF_LSM + (row * 8 + i) * 2] - M);
    g_scratch[OFF_LSM + 1024 + row] = M + logf(S);
}

__global__ void lsm3_k(float* __restrict__ y) {
    int row = blockIdx.y;
    int base = blockIdx.x * 1024;
    float lse = g_scratch[OFF_LSM + 1024 + row];
    float* r = y + (size_t)row * V_;
    for (int i = base + threadIdx.x; i < min(base + 1024, V_); i += 256)
        r[i] -= lse;
}

// ---------------------------------------------------------------------------
// Launch — multi-stream fork/join inside graph capture
// ---------------------------------------------------------------------------
extern "C" void kernel_launch(void* const* d_in, const int* in_sizes, int n_in,
                              void* d_out, int out_size) {
    const int*   ids  = (const int*)d_in[0];
    const float* h    = (const float*)d_in[1];
    const float* c    = (const float*)d_in[2];
    const float* k    = (const float*)d_in[3];
    const float* ctxv = (const float*)d_in[4];
    const float* enc  = (const float*)d_in[5];
    const float* emb  = (const float*)d_in[6];
    const float* W_ih = (const float*)d_in[7];
    const float* W_hh = (const float*)d_in[8];
    const float* b_ih = (const float*)d_in[9];
    const float* b_hh = (const float*)d_in[10];
    const float* aW1  = (const float*)d_in[11];
    const float* ab1  = (const float*)d_in[12];
    const float* aW2  = (const float*)d_in[13];
    const float* ab2  = (const float*)d_in[14];
    const float* aW3  = (const float*)d_in[15];
    const float* ab3  = (const float*)d_in[16];
    const float* kW1  = (const float*)d_in[17];
    const float* kb1  = (const float*)d_in[18];
    const float* kW2  = (const float*)d_in[19];
    const float* kb2  = (const float*)d_in[20];
    const float* kW3  = (const float*)d_in[21];
    const float* kb3  = (const float*)d_in[22];
    const float* alW  = (const float*)d_in[23];
    const float* alb  = (const float*)d_in[24];

    float* y   = (float*)d_out;
    float* h_t = y + (size_t)B_ * V_;
    float* c_t = h_t + (size_t)B_ * H_;

    static cudaStream_t sK = nullptr, sV = nullptr;
    static cudaEvent_t evRoot = nullptr, evH = nullptr,
                       evVK = nullptr, evP1 = nullptr;
    if (!sK) {
        cudaStreamCreateWithFlags(&sK, cudaStreamNonBlocking);
        cudaStreamCreateWithFlags(&sV, cudaStreamNonBlocking);
        cudaEventCreateWithFlags(&evRoot, cudaEventDisableTiming);
        cudaEventCreateWithFlags(&evH,    cudaEventDisableTiming);
        cudaEventCreateWithFlags(&evVK,   cudaEventDisableTiming);
        cudaEventCreateWithFlags(&evP1,   cudaEventDisableTiming);
        cudaFuncSetAttribute(tgemm_ca_k, cudaFuncAttributeMaxDynamicSharedMemorySize,
                             CA_SMEM_BYTES);
        cudaFuncSetAttribute(tgemm_bf16a_k, cudaFuncAttributeMaxDynamicSharedMemorySize,
                             UA_SMEM_BYTES);
        cudaFuncSetAttribute(vgemm_k, cudaFuncAttributeMaxDynamicSharedMemorySize,
                             VG_SMEM_BYTES);
        cudaFuncSetAttribute(gates_k, cudaFuncAttributeMaxDynamicSharedMemorySize,
                             8 * 1536 * (int)sizeof(float));
    }

    // ---- fork ---------------------------------------------------------------
    cudaEventRecord(evRoot, 0);
    cudaStreamWaitEvent(sK, evRoot, 0);
    cudaStreamWaitEvent(sV, evRoot, 0);

    // stream K: LSTM-independent key-attention prep
    tgemm_ca_k<<<dim3(E_ / 128, (KV_ + 127) / 128), 256, CA_SMEM_BYTES, sK>>>(
        k, 0, kW1 + (size_t)2 * H_ * E_, E_, OFF_KPART, E_,
        KV_, E_, E_, nullptr, 0, 0, 1, 0, nullptr, 0);
    smallm_k<<<dim3(E_ / 256, B_), 256, H_ * sizeof(float), sK>>>(
        ctxv, kW1, OFF_BPART, E_, H_, 0);

    // stream 0: LSTM
    gates_k<<<dim3(G4H / 256, B_ / 8), 256, 8 * 1536 * sizeof(float)>>>(
        ids, emb, h, W_ih, W_hh, b_ih, b_hh);
    lstm_k<<<(B_ * H_) / 256, 256>>>(c, h_t, c_t);
    cudaEventRecord(evH, 0);
    cudaStreamWaitEvent(sK, evH, 0);
    cudaStreamWaitEvent(sV, evH, 0);

    // stream V: vocab GEMM pass 1 (h_t half)
    vgemm_k<<<(V_ + 255) / 256, 256, VG_SMEM_BYTES, sV>>>(
        alW, alb, y, h_t, 0, H_, H_ / 16, 0, 0);
    cudaEventRecord(evP1, sV);

    // stream K: key-attention chain (UK1 in paired bf16)
    smallm_k<<<dim3(E_ / 256, B_), 256, H_ * sizeof(float), sK>>>(
        h_t, kW1 + (size_t)H_ * E_, OFF_BPART, E_, H_, 1);
    uk1_k<<<(B_ * KV_ * 64) / 256, 256, 0, sK>>>(kb1);
    tgemm_bf16a_k<<<dim3(E_ / 128, (B_ * KV_) / 128), 256, UA_SMEM_BYTES, sK>>>(
        kW2, kb2, kW3, OFF_UK2);
    reduce_k<<<(B_ * KV_ + 255) / 256, 256, 0, sK>>>(OFF_UK2, OFF_VK, B_ * KV_, 16, kb3);
    cudaEventRecord(evVK, sK);

    // stream 0: additive attention chain
    smallm_k<<<dim3(E_ / 256, B_), 256, H_ * sizeof(float)>>>(
        h_t, aW1 + (size_t)H_ * E_, OFF_HB, E_, H_, 0);
    tgemm_ca_k<<<dim3(E_ / 128, (B_ * L_) / 128), 256, CA_SMEM_BYTES>>>(
        enc, 0, aW1, E_, OFF_U1, E_,
        B_ * L_, E_, H_, ab1, 1, OFF_HB, L_, 1, nullptr, 0);
    tgemm_ca_k<<<dim3(E_ / 128, (B_ * L_) / 128), 256, CA_SMEM_BYTES>>>(
        nullptr, OFF_U1, aW2, E_, 0, 0,
        B_ * L_, E_, E_, ab2, 0, 0, 1, 1, aW3, OFF_U2);
    reduce_k<<<(B_ * L_) / 256, 256>>>(OFF_U2, OFF_SC, B_ * L_, 16, ab3);
    softmax_k<<<B_, 256>>>();
    ctx_k<<<dim3(H_ / 256, B_), 256>>>(enc);

    // join: vocab GEMM pass 2 (hctx half + vk, accumulate)
    cudaStreamWaitEvent(0, evVK, 0);
    cudaStreamWaitEvent(0, evP1, 0);
    vgemm_k<<<(V_ + 255) / 256, 256, VG_SMEM_BYTES>>>(
        alW + (size_t)H_ * V_, nullptr, y, nullptr, OFF_HCTX, H_, H_ / 16, 1, 1);

    // parallel log-softmax
    lsm1_k<<<dim3(8, B_), 256>>>(y);
    lsm2_k<<<1, B_>>>();
    lsm3_k<<<dim3((V_ + 1023) / 1024, B_), 256>>>(y);
}

// round 17
// speedup vs baseline: 1.1206x; 1.0135x over previous
#include <cuda_runtime.h>
#include <math.h>
#include <stdint.h>

// ---------------------------------------------------------------------------
// Problem constants
// ---------------------------------------------------------------------------
constexpr int B_  = 64;
constexpr int H_  = 1024;
constexpr int E_  = 512;
constexpr int V_  = 50257;
constexpr int KV_ = 1000;
constexpr int L_  = 512;
constexpr int G4H = 4 * H_;   // 4096

// ---------------------------------------------------------------------------
// Scratch arena
// ---------------------------------------------------------------------------
constexpr long OFF_GATES = 0;
constexpr long OFF_HB    = OFF_GATES + (long)B_ * G4H;
constexpr long OFF_U1    = OFF_HB    + (long)B_ * E_;
constexpr long OFF_U2    = OFF_U1    + (long)B_ * L_ * E_;   // attn dot partials
constexpr long OFF_SC    = OFF_U2    + (long)B_ * L_ * E_;
constexpr long OFF_HCTX  = OFF_SC    + (long)B_ * L_;
constexpr long OFF_KPART = OFF_HCTX  + (long)B_ * H_;
constexpr long OFF_BPART = OFF_KPART + (long)KV_ * E_;
constexpr long OFF_UK1   = OFF_BPART + (long)B_ * E_;        // bf16 paired (uses half)
constexpr long OFF_UK2   = OFF_UK1   + (long)B_ * KV_ * E_;  // key dot partials
constexpr long OFF_VK    = OFF_UK2   + (long)B_ * KV_ * E_;
constexpr long OFF_LSM   = OFF_VK    + (long)B_ * KV_;
constexpr long SCRATCH_TOTAL = OFF_LSM + 2048;

__device__ __align__(16) float g_scratch[SCRATCH_TOTAL];

// ---------------------------------------------------------------------------
// Helpers
// ---------------------------------------------------------------------------
static __device__ __forceinline__ float sigmoidf_(float x) {
    return 1.0f / (1.0f + expf(-x));
}

static __device__ __forceinline__ uint32_t smem_u32(const void* p) {
    return (uint32_t)__cvta_generic_to_shared(p);
}

static __device__ __forceinline__ void cp_async16(uint32_t dst, const void* src, int szBytes) {
    asm volatile("cp.async.cg.shared.global [%0], [%1], 16, %2;\n"
                 :: "r"(dst), "l"(src), "r"(szBytes) : "memory");
}

static __device__ __forceinline__ float blockReduceMax(float v, float* red, int tid) {
    #pragma unroll
    for (int o = 16; o; o >>= 1) v = fmaxf(v, __shfl_xor_sync(0xffffffffu, v, o));
    if ((tid & 31) == 0) red[tid >> 5] = v;
    __syncthreads();
    int nw = blockDim.x >> 5;
    float r = red[0];
    for (int i = 1; i < nw; i++) r = fmaxf(r, red[i]);
    __syncthreads();
    return r;
}

static __device__ __forceinline__ float blockReduceSum(float v, float* red, int tid) {
    #pragma unroll
    for (int o = 16; o; o >>= 1) v += __shfl_xor_sync(0xffffffffu, v, o);
    if ((tid & 31) == 0) red[tid >> 5] = v;
    __syncthreads();
    int nw = blockDim.x >> 5;
    float r = red[0];
    for (int i = 1; i < nw; i++) r += red[i];
    __syncthreads();
    return r;
}

// ---------------------------------------------------------------------------
// LSTM gates
// ---------------------------------------------------------------------------
__global__ void gates_k(const int* __restrict__ ids, const float* __restrict__ emb,
                        const float* __restrict__ h, const float* __restrict__ W_ih,
                        const float* __restrict__ W_hh, const float* __restrict__ b_ih,
                        const float* __restrict__ b_hh) {
    extern __shared__ float xh[];    // [8][1536]
    const int tid = threadIdx.x;
    const int b0 = blockIdx.y * 8;
    for (int i = tid; i < 8 * E_; i += 256) {
        int bi = i >> 9, e = i & (E_ - 1);
        xh[bi * 1536 + e] = emb[(long)ids[b0 + bi] * E_ + e];
    }
    for (int i = tid; i < 8 * H_; i += 256) {
        int bi = i >> 10, e = i & (H_ - 1);
        xh[bi * 1536 + E_ + e] = h[(size_t)(b0 + bi) * H_ + e];
    }
    __syncthreads();
    const int col = blockIdx.x * 256 + tid;
    float bias = b_ih[col] + b_hh[col];
    float acc[8];
    #pragma unroll
    for (int bi = 0; bi < 8; bi++) acc[bi] = bias;
    for (int e = 0; e < 1536; e++) {
        float w = (e < E_) ? W_ih[(size_t)e * G4H + col]
                           : W_hh[(size_t)(e - E_) * G4H + col];
        #pragma unroll
        for (int bi = 0; bi < 8; bi++)
            acc[bi] = fmaf(xh[bi * 1536 + e], w, acc[bi]);
    }
    #pragma unroll
    for (int bi = 0; bi < 8; bi++)
        g_scratch[OFF_GATES + (size_t)(b0 + bi) * G4H + col] = acc[bi];
}

// ---------------------------------------------------------------------------
// LSTM elementwise (gate order i, f, g, o)
// ---------------------------------------------------------------------------
__global__ void lstm_k(const float* __restrict__ c_in,
                       float* __restrict__ h_t, float* __restrict__ c_t) {
    int idx = blockIdx.x * 256 + threadIdx.x;
    int b = idx >> 10, j = idx & 1023;
    const float* g = g_scratch + OFF_GATES + (size_t)b * G4H;
    float ig = sigmoidf_(g[j]);
    float fg = sigmoidf_(g[H_ + j]);
    float gg = tanhf(g[2 * H_ + j]);
    float og = sigmoidf_(g[3 * H_ + j]);
    float ct = fg * c_in[idx] + ig * gg;
    c_t[idx] = ct;
    h_t[idx] = og * tanhf(ct);
}

// ---------------------------------------------------------------------------
// Small-M GEMM (one row per blockIdx.y — weight panel is L2-resident)
// ---------------------------------------------------------------------------
__global__ void smallm_k(const float* __restrict__ A, const float* __restrict__ Bm,
                         long Coff, int N, int K, int accumulate) {
    extern __shared__ float As[];
    float* C = g_scratch + Coff;
    int m = blockIdx.y;
    for (int i = threadIdx.x; i < K; i += blockDim.x) As[i] = A[(size_t)m * K + i];
    __syncthreads();
    int col = blockIdx.x * blockDim.x + threadIdx.x;
    float acc = accumulate ? C[(size_t)m * N + col] : 0.0f;
    #pragma unroll 4
    for (int kk = 0; kk < K; kk++)
        acc = fmaf(As[kk], Bm[(size_t)kk * N + col], acc);
    C[(size_t)m * N + col] = acc;
}

// ---------------------------------------------------------------------------
// TF32 GEMM, 128x128 tile, 4-stage cp.async, 2 CTAs/SM (proven config)
// ---------------------------------------------------------------------------
constexpr int CA_ASTRIDE = 20;
constexpr int CA_ASZ = 128 * CA_ASTRIDE;
constexpr int CA_BSZ = 16 * 128;
constexpr int CA_STAGES = 4;
constexpr int CA_SMEM_BYTES = CA_STAGES * (CA_ASZ + CA_BSZ) * 4;   // 73728

__global__ __launch_bounds__(256, 2) void tgemm_ca_k(
    const float* __restrict__ Ap, long Aoff,
    const float* __restrict__ Bm, int ldb,
    long Coff, int ldc,
    int M, int N, int K,
    const float* __restrict__ bias,
    int useRowAdd, long rowAddOff, int rowDiv,
    int doTanh,
    const float* __restrict__ dotW, long dotOff) {

    extern __shared__ float smem[];
    float* Abase = smem;
    float* Bbase = smem + CA_STAGES * CA_ASZ;

    const float* A = Ap ? Ap : (const float*)g_scratch + Aoff;

    const int tid  = threadIdx.x;
    const int wid  = tid >> 5;
    const int lane = tid & 31;
    const int warp_m = wid & 1;
    const int warp_n = wid >> 1;
    const int g   = lane >> 2;
    const int tig = lane & 3;

    const int bm = blockIdx.y * 128;
    const int bn = blockIdx.x * 128;
    const int nsteps = K >> 4;

    float acc[4][4][4];
    #pragma unroll
    for (int i = 0; i < 4; i++)
        #pragma unroll
        for (int j = 0; j < 4; j++)
            #pragma unroll
            for (int r = 0; r < 4; r++) acc[i][j][r] = 0.0f;

    const int aRow0 = tid >> 2;
    const int aC    = (tid & 3) * 4;
    const int bK0   = tid >> 5;
    const int bCn   = tid & 31;

    auto issue = [&](int buf, int kstep) {
        if (kstep < nsteps) {
            const int k0 = kstep << 4;
            float* Ad = Abase + buf * CA_ASZ;
            float* Bd = Bbase + buf * CA_BSZ;
            #pragma unroll
            for (int it = 0; it < 2; it++) {
                int row = aRow0 + it * 64;
                int rg = bm + row;
                int ok = rg < M;
                int rc = ok ? rg : (M - 1);
                cp_async16(smem_u32(Ad + row * CA_ASTRIDE + aC),
                           A + (size_t)rc * K + k0 + aC, ok ? 16 : 0);
            }
            #pragma unroll
            for (int it = 0; it < 2; it++) {
                int kr = bK0 + it * 8;
                uint32_t grp = (uint32_t)(bCn >> 1) ^ (uint32_t)(kr & 3);
                cp_async16(smem_u32(Bd + kr * 128 + grp * 8 + (bCn & 1) * 4),
                           Bm + (size_t)(k0 + kr) * ldb + bn + bCn * 4, 16);
            }
        }
        asm volatile("cp.async.commit_group;\n" ::: "memory");
    };

    int bcol[4];
    #pragma unroll
    for (int nti = 0; nti < 4; nti++)
        bcol[nti] = g + 8 * ((warp_n * 4 + nti) ^ tig);
    const int am0 = (warp_m * 64 + g) * CA_ASTRIDE;

    auto compute = [&](int buf) {
        const float* At = Abase + buf * CA_ASZ;
        const float* Bt = Bbase + buf * CA_BSZ;
        #pragma unroll
        for (int kt = 0; kt < 2; kt++) {
            const int k0 = kt * 8 + tig;
            float b0[4], b1[4];
            #pragma unroll
            for (int nti = 0; nti < 4; nti++) {
                b0[nti] = Bt[k0 * 128 + bcol[nti]];
                b1[nti] = Bt[(k0 + 4) * 128 + bcol[nti]];
            }
            #pragma unroll
            for (int mti = 0; mti < 4; mti++) {
                const float* Ar = At + am0 + mti * 16 * CA_ASTRIDE;
                float a0 = Ar[k0];
                float a1 = Ar[8 * CA_ASTRIDE + k0];
                float a2 = Ar[k0 + 4];
                float a3 = Ar[8 * CA_ASTRIDE + k0 + 4];
                #pragma unroll
                for (int nti = 0; nti < 4; nti++) {
                    asm volatile(
                        "mma.sync.aligned.m16n8k8.row.col.f32.tf32.tf32.f32 "
                        "{%0,%1,%2,%3}, {%4,%5,%6,%7}, {%8,%9}, {%0,%1,%2,%3};"
                        : "+f"(acc[mti][nti][0]), "+f"(acc[mti][nti][1]),
                          "+f"(acc[mti][nti][2]), "+f"(acc[mti][nti][3])
                        : "r"(__float_as_uint(a0)), "r"(__float_as_uint(a1)),
                          "r"(__float_as_uint(a2)), "r"(__float_as_uint(a3)),
                          "r"(__float_as_uint(b0[nti])), "r"(__float_as_uint(b1[nti])));
                }
            }
        }
    };

    issue(0, 0);
    issue(1, 1);
    issue(2, 2);

    #pragma unroll 4
    for (int s = 0; s < nsteps; s++) {
        asm volatile("cp.async.wait_group 2;\n" ::: "memory");
        __syncthreads();
        int nb = s + 3;
        issue(nb & 3, nb);
        compute(s & 3);
    }

    if (dotW) {
        float wv[4][2], bv[4][2];
        #pragma unroll
        for (int nti = 0; nti < 4; nti++)
            #pragma unroll
            for (int b2 = 0; b2 < 2; b2++) {
                int col = bn + warp_n * 32 + nti * 8 + tig * 2 + b2;
                wv[nti][b2] = dotW[col];
                bv[nti][b2] = bias ? bias[col] : 0.0f;
            }
        float part[4][2];
        #pragma unroll
        for (int i = 0; i < 4; i++) { part[i][0] = 0.f; part[i][1] = 0.f; }
        #pragma unroll
        for (int mti = 0; mti < 4; mti++)
            #pragma unroll
            for (int r = 0; r < 4; r++) {
                int rh = r >> 1;
                int cb = r & 1;
                #pragma unroll
                for (int nti = 0; nti < 4; nti++) {
                    float v = acc[mti][nti][r] + bv[nti][cb];
                    if (doTanh) v = tanhf(v);
                    part[mti][rh] = fmaf(v, wv[nti][cb], part[mti][rh]);
                }
            }
        #pragma unroll
        for (int i = 0; i < 4; i++) {
            #pragma unroll
            for (int rh = 0; rh < 2; rh++) {
                part[i][rh] += __shfl_xor_sync(0xffffffffu, part[i][rh], 1);
                part[i][rh] += __shfl_xor_sync(0xffffffffu, part[i][rh], 2);
            }
        }
        if (tig == 0) {
            float* buf = g_scratch + dotOff +
                         (size_t)(blockIdx.x * 4 + warp_n) * M;
            #pragma unroll
            for (int mti = 0; mti < 4; mti++)
                #pragma unroll
                for (int rh = 0; rh < 2; rh++) {
                    int row = bm + warp_m * 64 + mti * 16 + g + rh * 8;
                    if (row < M) buf[row] = part[mti][rh];
                }
        }
        return;
    }

    float* Co = g_scratch + Coff;
    const float* raB = useRowAdd ? (const float*)g_scratch + rowAddOff : nullptr;
    #pragma unroll
    for (int mti = 0; mti < 4; mti++) {
        #pragma unroll
        for (int r = 0; r < 4; r++) {
            int row = bm + warp_m * 64 + mti * 16 + g + ((r >= 2) ? 8 : 0);
            if (row >= M) continue;
            const float* ra = raB ? raB + (size_t)(row / rowDiv) * N : nullptr;
            #pragma unroll
            for (int nti = 0; nti < 4; nti++) {
                int col = bn + warp_n * 32 + nti * 8 + tig * 2 + (r & 1);
                float v = acc[mti][nti][r];
                if (bias) v += bias[col];
                if (ra) v += ra[col];
                if (doTanh) v = tanhf(v);
                Co[(size_t)row * ldc + col] = v;
            }
        }
    }
}

// ---------------------------------------------------------------------------
// uk2 GEMM with bf16 A (paired layout from uk1_k), proven R15 config.
// ---------------------------------------------------------------------------
constexpr int UA_ASZ = 1024;   // uint32 per A stage
constexpr int UA_SMEM_BYTES = CA_STAGES * (UA_ASZ + CA_BSZ) * 4;   // 49152

__global__ __launch_bounds__(256, 2) void tgemm_bf16a_k(
    const float* __restrict__ Bm,      // kW2 [512,512]
    const float* __restrict__ bias,    // kb2
    const float* __restrict__ dotW,    // kW3
    long dotOff) {

    extern __shared__ float smem[];
    uint32_t* Abase = (uint32_t*)smem;
    float* Bbase = smem + CA_STAGES * UA_ASZ;

    const uint32_t* Ag = (const uint32_t*)(g_scratch + OFF_UK1);

    const int tid  = threadIdx.x;
    const int wid  = tid >> 5;
    const int lane = tid & 31;
    const int warp_m = wid & 1;
    const int warp_n = wid >> 1;
    const int g   = lane >> 2;
    const int tig = lane & 3;

    const int bm = blockIdx.y * 128;
    const int bn = blockIdx.x * 128;
    const int M = B_ * KV_;
    constexpr int nsteps = E_ >> 4;    // 32

    float acc[4][4][4];
    #pragma unroll
    for (int i = 0; i < 4; i++)
        #pragma unroll
        for (int j = 0; j < 4; j++)
            #pragma unroll
            for (int r = 0; r < 4; r++) acc[i][j][r] = 0.0f;

    const int aRow  = tid >> 1;
    const int aHalf = tid & 1;
    const int bK0   = tid >> 5;
    const int bCn   = tid & 31;

    auto issue = [&](int buf, int kstep) {
        if (kstep < nsteps) {
            uint32_t* Ad = Abase + buf * UA_ASZ;
            float* Bd = Bbase + buf * CA_BSZ;
            cp_async16(smem_u32(Ad + aHalf * 512 + aRow * 4),
                       Ag + (size_t)(bm + aRow) * 256 + kstep * 8 + aHalf * 4, 16);
            const int k0 = kstep << 4;
            #pragma unroll
            for (int it = 0; it < 2; it++) {
                int kr = bK0 + it * 8;
                uint32_t grp = (uint32_t)(bCn >> 1) ^ (uint32_t)(kr & 3);
                cp_async16(smem_u32(Bd + kr * 128 + grp * 8 + (bCn & 1) * 4),
                           Bm + (size_t)(k0 + kr) * E_ + bn + bCn * 4, 16);
            }
        }
        asm volatile("cp.async.commit_group;\n" ::: "memory");
    };

    int bcol[4];
    #pragma unroll
    for (int nti = 0; nti < 4; nti++)
        bcol[nti] = g + 8 * ((warp_n * 4 + nti) ^ tig);

    auto compute = [&](int buf) {
        const uint32_t* At = Abase + buf * UA_ASZ;
        const float* Bt = Bbase + buf * CA_BSZ;
        #pragma unroll
        for (int kt = 0; kt < 2; kt++) {
            const int k0 = kt * 8 + tig;
            float b0[4], b1[4];
            #pragma unroll
            for (int nti = 0; nti < 4; nti++) {
                b0[nti] = Bt[k0 * 128 + bcol[nti]];
                b1[nti] = Bt[(k0 + 4) * 128 + bcol[nti]];
            }
            const uint32_t* Ak = At + kt * 512 + tig;
            #pragma unroll
            for (int mti = 0; mti < 4; mti++) {
                int row0 = warp_m * 64 + mti * 16 + g;
                uint32_t u0 = Ak[row0 * 4];
                uint32_t u1 = Ak[(row0 + 8) * 4];
                float a0 = __uint_as_float(u0 << 16);
                float a2 = __uint_as_float(u0 & 0xffff0000u);
                float a1 = __uint_as_float(u1 << 16);
                float a3 = __uint_as_float(u1 & 0xffff0000u);
                #pragma unroll
                for (int nti = 0; nti < 4; nti++) {
                    asm volatile(
                        "mma.sync.aligned.m16n8k8.row.col.f32.tf32.tf32.f32 "
                        "{%0,%1,%2,%3}, {%4,%5,%6,%7}, {%8,%9}, {%0,%1,%2,%3};"
                        : "+f"(acc[mti][nti][0]), "+f"(acc[mti][nti][1]),
                          "+f"(acc[mti][nti][2]), "+f"(acc[mti][nti][3])
                        : "r"(__float_as_uint(a0)), "r"(__float_as_uint(a1)),
                          "r"(__float_as_uint(a2)), "r"(__float_as_uint(a3)),
                          "r"(__float_as_uint(b0[nti])), "r"(__float_as_uint(b1[nti])));
                }
            }
        }
    };

    issue(0, 0);
    issue(1, 1);
    issue(2, 2);

    #pragma unroll 4
    for (int s = 0; s < nsteps; s++) {
        asm volatile("cp.async.wait_group 2;\n" ::: "memory");
        __syncthreads();
        int nb = s + 3;
        issue(nb & 3, nb);
        compute(s & 3);
    }

    float wv[4][2], bv[4][2];
    #pragma unroll
    for (int nti = 0; nti < 4; nti++)
        #pragma unroll
        for (int b2 = 0; b2 < 2; b2++) {
            int col = bn + warp_n * 32 + nti * 8 + tig * 2 + b2;
            wv[nti][b2] = dotW[col];
            bv[nti][b2] = bias[col];
        }
    float part[4][2];
    #pragma unroll
    for (int i = 0; i < 4; i++) { part[i][0] = 0.f; part[i][1] = 0.f; }
    #pragma unroll
    for (int mti = 0; mti < 4; mti++)
        #pragma unroll
        for (int r = 0; r < 4; r++) {
            int rh = r >> 1;
            int cb = r & 1;
            #pragma unroll
            for (int nti = 0; nti < 4; nti++) {
                float v = tanhf(acc[mti][nti][r] + bv[nti][cb]);
                part[mti][rh] = fmaf(v, wv[nti][cb], part[mti][rh]);
            }
        }
    #pragma unroll
    for (int i = 0; i < 4; i++) {
        #pragma unroll
        for (int rh = 0; rh < 2; rh++) {
            part[i][rh] += __shfl_xor_sync(0xffffffffu, part[i][rh], 1);
            part[i][rh] += __shfl_xor_sync(0xffffffffu, part[i][rh], 2);
        }
    }
    if (tig == 0) {
        float* buf = g_scratch + dotOff + (size_t)(blockIdx.x * 4 + warp_n) * M;
        #pragma unroll
        for (int mti = 0; mti < 4; mti++)
            #pragma unroll
            for (int rh = 0; rh < 2; rh++) {
                int row = bm + warp_m * 64 + mti * 16 + g + rh * 8;
                buf[row] = part[mti][rh];
            }
    }
}

// ---------------------------------------------------------------------------
// reduce_k: out[row] = sum_{i<P} buf[i*M + row] + b[0]
// ---------------------------------------------------------------------------
__global__ void reduce_k(long bufOff, long outOff, int M, int P,
                         const float* __restrict__ bptr) {
    int row = blockIdx.x * 256 + threadIdx.x;
    if (row >= M) return;
    const float* buf = (const float*)g_scratch + bufOff;
    float s = bptr[0];
    for (int i = 0; i < P; i++) s += buf[(size_t)i * M + row];
    g_scratch[outOff + row] = s;
}

// ---------------------------------------------------------------------------
// Vocab GEMM half: y[64, V] (+)= A[64, :1024] @ Bm[1024, V] (+bias)(+vk)
// B rows loaded as ALIGNED 16B windows (65 chunks of 4 floats, window start
// = (k*V + bn) rounded down to 16B; store LINEAR at row*264 + delta + col,
// consumer adds delta = k mod 4 = tig -> bcol has NO xor swizzle).
// Partial boundary chunks copy a valid prefix and zero-fill the rest.
// ---------------------------------------------------------------------------
constexpr int VG_ASTRIDE = 20;
constexpr int VG_ASZ  = 64 * VG_ASTRIDE;   // 1280 floats / stage
constexpr int VG_BROW = 264;               // 260 floats window + pad
constexpr int VG_BSZ  = 16 * VG_BROW;      // 4224 floats / stage
constexpr int VG_STAGES = 4;
constexpr int VG_SMEM_BYTES = VG_STAGES * (VG_ASZ + VG_BSZ) * 4;  // 88064 B

__global__ __launch_bounds__(256, 2) void vgemm_k(
    const float* __restrict__ Bm,
    const float* __restrict__ bias,
    float* __restrict__ y,
    const float* __restrict__ Aopt, long Aoff, int lda,
    int nsteps, int addTo, int useVk, long boundFloats) {

    extern __shared__ float smem[];
    float* Abase = smem;
    float* Bbase = smem + VG_STAGES * VG_ASZ;

    const float* A = Aopt ? Aopt : (const float*)g_scratch + Aoff;

    const int tid  = threadIdx.x;
    const int wid  = tid >> 5;
    const int lane = tid & 31;
    const int g    = lane >> 2;
    const int tig  = lane & 3;

    const int bn = blockIdx.x * 256;

    float acc[4][4][4];
    #pragma unroll
    for (int i = 0; i < 4; i++)
        #pragma unroll
        for (int j = 0; j < 4; j++)
            #pragma unroll
            for (int r = 0; r < 4; r++) acc[i][j][r] = 0.0f;

    const int aRow = tid >> 2;
    const int aC   = (tid & 3) * 4;

    // precomputed B-chunk slots: 16 rows x 65 chunks = 1040 over 5 passes
    int crow[5], cchk[5];
    #pragma unroll
    for (int it = 0; it < 5; it++) {
        int idx = it * 256 + tid;
        crow[it] = idx / 65;
        cchk[it] = idx - crow[it] * 65;
    }

    auto issue = [&](int buf, int kstep) {
        if (kstep < nsteps) {
            const int k0 = kstep << 4;
            float* Ad = Abase + buf * VG_ASZ;
            float* Bd = Bbase + buf * VG_BSZ;
            cp_async16(smem_u32(Ad + aRow * VG_ASTRIDE + aC),
                       A + (size_t)aRow * lda + k0 + aC, 16);
            #pragma unroll
            for (int it = 0; it < 5; it++) {
                int row = crow[it];
                if (row < 16) {
                    long kq = (long)(k0 + row);
                    long o = kq * V_ + bn - (row & 3) + cchk[it] * 4;
                    long rem = boundFloats - o;
                    int sz = rem >= 4 ? 16 : (rem > 0 ? (int)(rem * 4) : 0);
                    long oc = (rem > 0) ? o : 0;
                    cp_async16(smem_u32(Bd + row * VG_BROW + cchk[it] * 4),
                               Bm + oc, sz);
                }
            }
        }
        asm volatile("cp.async.commit_group;\n" ::: "memory");
    };

    // linear store -> NO xor swizzle in read; +tig is the alignment delta
    int bcol[4];
    #pragma unroll
    for (int nti = 0; nti < 4; nti++)
        bcol[nti] = g + 8 * (wid * 4 + nti) + tig;
    const int am0 = g * VG_ASTRIDE;

    auto compute = [&](int buf) {
        const float* At = Abase + buf * VG_ASZ;
        const float* Bt = Bbase + buf * VG_BSZ;
        #pragma unroll
        for (int kt = 0; kt < 2; kt++) {
            const int k0 = kt * 8 + tig;
            float b0[4], b1[4];
            #pragma unroll
            for (int nti = 0; nti < 4; nti++) {
                b0[nti] = Bt[k0 * VG_BROW + bcol[nti]];
                b1[nti] = Bt[(k0 + 4) * VG_BROW + bcol[nti]];
            }
            #pragma unroll
            for (int mti = 0; mti < 4; mti++) {
                const float* Ar = At + am0 + mti * 16 * VG_ASTRIDE;
                float a0 = Ar[k0];
                float a1 = Ar[8 * VG_ASTRIDE + k0];
                float a2 = Ar[k0 + 4];
                float a3 = Ar[8 * VG_ASTRIDE + k0 + 4];
                #pragma unroll
                for (int nti = 0; nti < 4; nti++) {
                    asm volatile(
                        "mma.sync.aligned.m16n8k8.row.col.f32.tf32.tf32.f32 "
                        "{%0,%1,%2,%3}, {%4,%5,%6,%7}, {%8,%9}, {%0,%1,%2,%3};"
                        : "+f"(acc[mti][nti][0]), "+f"(acc[mti][nti][1]),
                          "+f"(acc[mti][nti][2]), "+f"(acc[mti][nti][3])
                        : "r"(__float_as_uint(a0)), "r"(__float_as_uint(a1)),
                          "r"(__float_as_uint(a2)), "r"(__float_as_uint(a3)),
                          "r"(__float_as_uint(b0[nti])), "r"(__float_as_uint(b1[nti])));
                }
            }
        }
    };

    issue(0, 0);
    issue(1, 1);
    issue(2, 2);

    #pragma unroll 4
    for (int s = 0; s < nsteps; s++) {
        asm volatile("cp.async.wait_group 2;\n" ::: "memory");
        __syncthreads();
        int nb = s + 3;
        issue(nb & 3, nb);
        compute(s & 3);
    }

    #pragma unroll
    for (int mti = 0; mti < 4; mti++) {
        #pragma unroll
        for (int r = 0; r < 4; r++) {
            int row = mti * 16 + g + ((r >= 2) ? 8 : 0);
            #pragma unroll
            for (int nti = 0; nti < 4; nti++) {
                int col = bn + wid * 32 + nti * 8 + tig * 2 + (r & 1);
                if (col >= V_) continue;
                float v = acc[mti][nti][r];
                if (bias) v += bias[col];
                if (addTo) v += y[(size_t)row * V_ + col];
                if (useVk) {
                    int kc = col - (V_ - KV_);
                    if (kc >= 0) v += g_scratch[OFF_VK + (size_t)row * KV_ + kc];
                }
                y[(size_t)row * V_ + col] = v;
            }
        }
    }
}

// ---------------------------------------------------------------------------
// softmax over L=512
// ---------------------------------------------------------------------------
__global__ void softmax_k() {
    __shared__ float red[32];
    float* row = g_scratch + OFF_SC + (size_t)blockIdx.x * L_;
    int tid = threadIdx.x;
    float v0 = row[tid], v1 = row[tid + 256];
    float m = blockReduceMax(fmaxf(v0, v1), red, tid);
    float e0 = expf(v0 - m), e1 = expf(v1 - m);
    float s = blockReduceSum(e0 + e1, red, tid);
    float inv = 1.0f / s;
    row[tid] = e0 * inv;
    row[tid + 256] = e1 * inv;
}

// ---------------------------------------------------------------------------
// h_ctx[b, col] = sum_l a[b,l] * enc[b,l,col]
// ---------------------------------------------------------------------------
__global__ void ctx_k(const float* __restrict__ enc) {
    __shared__ float as[L_];
    int b = blockIdx.y, tid = threadIdx.x;
    for (int i = tid; i < L_; i += 256) as[i] = g_scratch[OFF_SC + (size_t)b * L_ + i];
    __syncthreads();
    int col = blockIdx.x * 256 + tid;
    const float* ep = enc + (size_t)b * L_ * H_ + col;
    float acc = 0.f;
    #pragma unroll 4
    for (int l = 0; l < L_; l++) acc = fmaf(as[l], ep[(size_t)l * H_], acc);
    g_scratch[OFF_HCTX + (size_t)b * H_ + col] = acc;
}

// ---------------------------------------------------------------------------
// uk1: UK1 (bf16, paired) [b*KV+kv][k] = tanh(bpart+kpart+kb1)
// ---------------------------------------------------------------------------
__global__ void uk1_k(const float* __restrict__ kb1) {
    size_t idx = (size_t)blockIdx.x * 256 + threadIdx.x;
    int g8 = (int)(idx & 63);
    size_t r = idx >> 6;
    int b = (int)(r / KV_);
    int kv = (int)(r - (size_t)b * KV_);
    int e = g8 * 8;
    const float* bp = g_scratch + OFF_BPART + (size_t)b * E_ + e;
    const float* kp = g_scratch + OFF_KPART + (size_t)kv * E_ + e;
    float4 b0 = *(const float4*)bp,  b1 = *(const float4*)(bp + 4);
    float4 k0 = *(const float4*)kp,  k1 = *(const float4*)(kp + 4);
    float4 c0 = *(const float4*)(kb1 + e), c1 = *(const float4*)(kb1 + e + 4);
    float t[8];
    t[0] = tanhf(b0.x + k0.x + c0.x);
    t[1] = tanhf(b0.y + k0.y + c0.y);
    t[2] = tanhf(b0.z + k0.z + c0.z);
    t[3] = tanhf(b0.w + k0.w + c0.w);
    t[4] = tanhf(b1.x + k1.x + c1.x);
    t[5] = tanhf(b1.y + k1.y + c1.y);
    t[6] = tanhf(b1.z + k1.z + c1.z);
    t[7] = tanhf(b1.w + k1.w + c1.w);
    uint32_t u[4];
    #pragma unroll
    for (int j = 0; j < 4; j++)
        asm("cvt.rn.bf16x2.f32 %0, %1, %2;"
            : "=r"(u[j]) : "f"(t[j + 4]), "f"(t[j]));
    uint4* dst = (uint4*)((uint32_t*)(g_scratch + OFF_UK1) + r * 256 + g8 * 4);
    *dst = make_uint4(u[0], u[1], u[2], u[3]);
}

// ---------------------------------------------------------------------------
// Parallel log-softmax, 3 phases.
// ---------------------------------------------------------------------------
constexpr int LSM_CHUNK = (V_ + 7) / 8;

__global__ void lsm1_k(const float* __restrict__ y) {
    __shared__ float red[32];
    int row = blockIdx.y, chunk = blockIdx.x, tid = threadIdx.x;
    int start = chunk * LSM_CHUNK;
    int end = min(start + LSM_CHUNK, V_);
    const float* r = y + (size_t)row * V_;
    float m = -INFINITY;
    for (int i = start + tid; i < end; i += 256) m = fmaxf(m, r[i]);
    m = blockReduceMax(m, red, tid);
    float s = 0.f;
    for (int i = start + tid; i < end; i += 256) s += expf(r[i] - m);
    s = blockReduceSum(s, red, tid);
    if (tid == 0) {
        g_scratch[OFF_LSM + (row * 8 + chunk) * 2]     = m;
        g_scratch[OFF_LSM + (row * 8 + chunk) * 2 + 1] = s;
    }
}

__global__ void lsm2_k() {
    int row = threadIdx.x;
    float M = -INFINITY;
    #pragma unroll
    for (int i = 0; i < 8; i++)
        M = fmaxf(M, g_scratch[OFF_LSM + (row * 8 + i) * 2]);
    float S = 0.f;
    #pragma unroll
    for (int i = 0; i < 8; i++)
        S += g_scratch[OFF_LSM + (row * 8 + i) * 2 + 1] *
             expf(g_scratch[OFF_LSM + (row * 8 + i) * 2] - M);
    g_scratch[OFF_LSM + 1024 + row] = M + logf(S);
}

__global__ void lsm3_k(float* __restrict__ y) {
    int row = blockIdx.y;
    int base = blockIdx.x * 1024;
    float lse = g_scratch[OFF_LSM + 1024 + row];
    float* r = y + (size_t)row * V_;
    for (int i = base + threadIdx.x; i < min(base + 1024, V_); i += 256)
        r[i] -= lse;
}

// ---------------------------------------------------------------------------
// Launch — multi-stream fork/join inside graph capture
// ---------------------------------------------------------------------------
extern "C" void kernel_launch(void* const* d_in, const int* in_sizes, int n_in,
                              void* d_out, int out_size) {
    const int*   ids  = (const int*)d_in[0];
    const float* h    = (const float*)d_in[1];
    const float* c    = (const float*)d_in[2];
    const float* k    = (const float*)d_in[3];
    const float* ctxv = (const float*)d_in[4];
    const float* enc  = (const float*)d_in[5];
    const float* emb  = (const float*)d_in[6];
    const float* W_ih = (const float*)d_in[7];
    const float* W_hh = (const float*)d_in[8];
    const float* b_ih = (const float*)d_in[9];
    const float* b_hh = (const float*)d_in[10];
    const float* aW1  = (const float*)d_in[11];
    const float* ab1  = (const float*)d_in[12];
    const float* aW2  = (const float*)d_in[13];
    const float* ab2  = (const float*)d_in[14];
    const float* aW3  = (const float*)d_in[15];
    const float* ab3  = (const float*)d_in[16];
    const float* kW1  = (const float*)d_in[17];
    const float* kb1  = (const float*)d_in[18];
    const float* kW2  = (const float*)d_in[19];
    const float* kb2  = (const float*)d_in[20];
    const float* kW3  = (const float*)d_in[21];
    const float* kb3  = (const float*)d_in[22];
    const float* alW  = (const float*)d_in[23];
    const float* alb  = (const float*)d_in[24];

    float* y   = (float*)d_out;
    float* h_t = y + (size_t)B_ * V_;
    float* c_t = h_t + (size_t)B_ * H_;

    static cudaStream_t sK = nullptr, sV = nullptr;
    static cudaEvent_t evRoot = nullptr, evH = nullptr,
                       evVK = nullptr, evP1 = nullptr;
    if (!sK) {
        cudaStreamCreateWithFlags(&sK, cudaStreamNonBlocking);
        cudaStreamCreateWithFlags(&sV, cudaStreamNonBlocking);
        cudaEventCreateWithFlags(&evRoot, cudaEventDisableTiming);
        cudaEventCreateWithFlags(&evH,    cudaEventDisableTiming);
        cudaEventCreateWithFlags(&evVK,   cudaEventDisableTiming);
        cudaEventCreateWithFlags(&evP1,   cudaEventDisableTiming);
        cudaFuncSetAttribute(tgemm_ca_k, cudaFuncAttributeMaxDynamicSharedMemorySize,
                             CA_SMEM_BYTES);
        cudaFuncSetAttribute(tgemm_bf16a_k, cudaFuncAttributeMaxDynamicSharedMemorySize,
                             UA_SMEM_BYTES);
        cudaFuncSetAttribute(vgemm_k, cudaFuncAttributeMaxDynamicSharedMemorySize,
                             VG_SMEM_BYTES);
        cudaFuncSetAttribute(gates_k, cudaFuncAttributeMaxDynamicSharedMemorySize,
                             8 * 1536 * (int)sizeof(float));
    }

    // ---- fork ---------------------------------------------------------------
    cudaEventRecord(evRoot, 0);
    cudaStreamWaitEvent(sK, evRoot, 0);
    cudaStreamWaitEvent(sV, evRoot, 0);

    // stream K: LSTM-independent key-attention prep
    tgemm_ca_k<<<dim3(E_ / 128, (KV_ + 127) / 128), 256, CA_SMEM_BYTES, sK>>>(
        k, 0, kW1 + (size_t)2 * H_ * E_, E_, OFF_KPART, E_,
        KV_, E_, E_, nullptr, 0, 0, 1, 0, nullptr, 0);
    smallm_k<<<dim3(E_ / 256, B_), 256, H_ * sizeof(float), sK>>>(
        ctxv, kW1, OFF_BPART, E_, H_, 0);

    // stream 0: LSTM
    gates_k<<<dim3(G4H / 256, B_ / 8), 256, 8 * 1536 * sizeof(float)>>>(
        ids, emb, h, W_ih, W_hh, b_ih, b_hh);
    lstm_k<<<(B_ * H_) / 256, 256>>>(c, h_t, c_t);
    cudaEventRecord(evH, 0);
    cudaStreamWaitEvent(sK, evH, 0);
    cudaStreamWaitEvent(sV, evH, 0);

    // stream V: vocab GEMM pass 1 (h_t half); bound = full alW (window
    // overreads land in the second half, still valid memory)
    vgemm_k<<<(V_ + 255) / 256, 256, VG_SMEM_BYTES, sV>>>(
        alW, alb, y, h_t, 0, H_, H_ / 16, 0, 0, (long)2048 * V_);
    cudaEventRecord(evP1, sV);

    // stream K: key-attention chain (UK1 in paired bf16)
    smallm_k<<<dim3(E_ / 256, B_), 256, H_ * sizeof(float), sK>>>(
        h_t, kW1 + (size_t)H_ * E_, OFF_BPART, E_, H_, 1);
    uk1_k<<<(B_ * KV_ * 64) / 256, 256, 0, sK>>>(kb1);
    tgemm_bf16a_k<<<dim3(E_ / 128, (B_ * KV_) / 128), 256, UA_SMEM_BYTES, sK>>>(
        kW2, kb2, kW3, OFF_UK2);
    reduce_k<<<(B_ * KV_ + 255) / 256, 256, 0, sK>>>(OFF_UK2, OFF_VK, B_ * KV_, 16, kb3);
    cudaEventRecord(evVK, sK);

    // stream 0: additive attention chain
    smallm_k<<<dim3(E_ / 256, B_), 256, H_ * sizeof(float)>>>(
        h_t, aW1 + (size_t)H_ * E_, OFF_HB, E_, H_, 0);
    tgemm_ca_k<<<dim3(E_ / 128, (B_ * L_) / 128), 256, CA_SMEM_BYTES>>>(
        enc, 0, aW1, E_, OFF_U1, E_,
        B_ * L_, E_, H_, ab1, 1, OFF_HB, L_, 1, nullptr, 0);
    tgemm_ca_k<<<dim3(E_ / 128, (B_ * L_) / 128), 256, CA_SMEM_BYTES>>>(
        nullptr, OFF_U1, aW2, E_, 0, 0,
        B_ * L_, E_, E_, ab2, 0, 0, 1, 1, aW3, OFF_U2);
    reduce_k<<<(B_ * L_) / 256, 256>>>(OFF_U2, OFF_SC, B_ * L_, 16, ab3);
    softmax_k<<<B_, 256>>>();
    ctx_k<<<dim3(H_ / 256, B_), 256>>>(enc);

    // join: vocab GEMM pass 2 (hctx half + vk, accumulate); bound = end of alW
    cudaStreamWaitEvent(0, evVK, 0);
    cudaStreamWaitEvent(0, evP1, 0);
    vgemm_k<<<(V_ + 255) / 256, 256, VG_SMEM_BYTES>>>(
        alW + (size_t)H_ * V_, nullptr, y, nullptr, OFF_HCTX, H_, H_ / 16, 1, 1,
        (long)1024 * V_);

    // parallel log-softmax
    lsm1_k<<<dim3(8, B_), 256>>>(y);
    lsm2_k<<<1, B_>>>();
    lsm3_k<<<dim3((V_ + 1023) / 1024, B_), 256>>>(y);
}